// round 12
// baseline (speedup 1.0000x reference)
#include <cuda_runtime.h>
#include <math.h>
#include <stdint.h>

#define BB     4
#define NN     1024
#define DIMC   512
#define DEPTHL 4
#define HEADS  8
#define DH     64
#define TCDD   512
#define HIDD   512
#define INNERC 2048
#define MAXREL 32
#define SCALEQ 0.125f
#define LNEPS  1e-5f

// ---------------- scratch ----------------------------------------------------
__device__ float g_tact[BB * TCDD];
__device__ float g_scsh_a[DEPTHL * BB * 2 * DIMC];
__device__ float g_scsh_f[DEPTHL * BB * 2 * INNERC];
__device__ float g_xn[BB * NN * DIMC];
__device__ float g_q[BB * NN * HIDD];
__device__ float g_kv[BB * NN * 2 * HIDD];
__device__ float g_ao[BB * NN * HIDD];
__device__ float g_hb[BB * NN * INNERC];
__device__ float g_wq[DEPTHL * DIMC * HIDD];
__device__ float g_wkv[DEPTHL * DIMC * 2 * HIDD];
__device__ float g_wo[DEPTHL * HIDD * DIMC];
__device__ float g_wfi[DEPTHL * DIMC * INNERC];
__device__ float g_wfo[DEPTHL * INNERC * DIMC];

// ---------------- helpers ----------------------------------------------------
__device__ __forceinline__ float tf32r(float x) {
    uint32_t u;
    asm("cvt.rna.tf32.f32 %0, %1;" : "=r"(u) : "f"(x));
    return __uint_as_float(u);
}

#define MMA_TF32(c, a0, a1, a2, a3, b0, b1)                                     \
    asm volatile(                                                               \
        "mma.sync.aligned.m16n8k8.row.col.f32.tf32.tf32.f32 "                   \
        "{%0,%1,%2,%3},{%4,%5,%6,%7},{%8,%9},{%0,%1,%2,%3};"                    \
        : "+f"(c[0]), "+f"(c[1]), "+f"(c[2]), "+f"(c[3])                        \
        : "r"(a0), "r"(a1), "r"(a2), "r"(a3), "r"(b0), "r"(b1))

#define CPA16(dst, src)                                                         \
    asm volatile("cp.async.cg.shared.global [%0], [%1], 16;" ::"r"(dst), "l"(src))
#define CP_COMMIT() asm volatile("cp.async.commit_group;")
#define CP_WAIT(n)  asm volatile("cp.async.wait_group %0;" ::"n"(n))

__device__ __forceinline__ uint32_t smem_u32(const void* p) {
    return (uint32_t)__cvta_generic_to_shared(p);
}

// ---------------- elementwise ------------------------------------------------
__global__ void round_all_k(const float* s0, float* d0, int n0,
                            const float* s1, float* d1, int n1,
                            const float* s2, float* d2, int n2,
                            const float* s3, float* d3, int n3,
                            const float* s4, float* d4, int n4) {
    int tid = blockIdx.x * 256 + threadIdx.x;
    int stride = gridDim.x * 256;
    const float* ss[5] = {s0, s1, s2, s3, s4};
    float* dd[5] = {d0, d1, d2, d3, d4};
    int nn[5] = {n0, n1, n2, n3, n4};
#pragma unroll
    for (int sgi = 0; sgi < 5; sgi++) {
        const float4* src = (const float4*)ss[sgi];
        float4* dst = (float4*)dd[sgi];
        int n = nn[sgi];
        for (int i = tid; i < n; i += stride) {
            float4 v = src[i];
            dst[i] = make_float4(tf32r(v.x), tf32r(v.y), tf32r(v.z), tf32r(v.w));
        }
    }
}

__global__ void silu_time_k(const float* __restrict__ tm, float* __restrict__ out) {
    int i = blockIdx.x * 256 + threadIdx.x;
    if (i < BB * TCDD) {
        float v = tm[i];
        out[i] = v / (1.f + __expf(-v));
    }
}

__global__ void init_x_k(const float* __restrict__ xin, const float* __restrict__ mask,
                         float* __restrict__ x) {
    int i = blockIdx.x * 256 + threadIdx.x;
    if (i < BB * NN * DIMC) x[i] = xin[i] * mask[i / DIMC];
}

// all layers' time-conditioning GEMVs. Block = 64 cols x 4 k-slices.
__global__ __launch_bounds__(256)
void time_all_k(const float* __restrict__ tact,
                const float* __restrict__ atw, const float* __restrict__ atb,
                const float* __restrict__ ftw, const float* __restrict__ ftb,
                float* __restrict__ scsh_a, float* __restrict__ scsh_f) {
    __shared__ float red[4][64];
    int colL = threadIdx.x & 63, kg = threadIdx.x >> 6;
    int col = blockIdx.x * 64 + colL;
    int b = blockIdx.y, d = blockIdx.z;
    const float* t = tact + b * TCDD + kg * 128;
    const float* W;
    const float* bias;
    float* out;
    int Ncols, c;
    if (col < 2 * DIMC) {
        Ncols = 2 * DIMC;
        c = col;
        W = atw + (size_t)d * TCDD * Ncols;
        bias = atb + (size_t)d * Ncols;
        out = scsh_a + ((size_t)d * BB + b) * Ncols;
    } else {
        Ncols = 2 * INNERC;
        c = col - 2 * DIMC;
        W = ftw + (size_t)d * TCDD * Ncols;
        bias = ftb + (size_t)d * Ncols;
        out = scsh_f + ((size_t)d * BB + b) * Ncols;
    }
    const float* Wp = W + (size_t)(kg * 128) * Ncols + c;
    float a0 = 0.f, a1 = 0.f;
#pragma unroll 4
    for (int k = 0; k < 128; k += 2) {
        a0 += t[k] * Wp[(size_t)k * Ncols];
        a1 += t[k + 1] * Wp[(size_t)(k + 1) * Ncols];
    }
    red[kg][colL] = a0 + a1;
    __syncthreads();
    if (kg == 0)
        out[c] = red[0][colL] + red[1][colL] + red[2][colL] + red[3][colL] + bias[c];
}

// Warp-per-row LayerNorm (+AdaLN mod, +row mask); output RNA-rounded.
__global__ __launch_bounds__(256)
void ln_mod_k(const float* __restrict__ x, const float* __restrict__ g,
              const float* __restrict__ scsh, const float* __restrict__ mask,
              float* __restrict__ out, int useMod) {
    int warp = threadIdx.x >> 5, lane = threadIdx.x & 31;
    int row = blockIdx.x * 8 + warp;
    const float* xr = x + (size_t)row * DIMC;
    float4 v[4];
    float s = 0.f, sq = 0.f;
#pragma unroll
    for (int i = 0; i < 4; i++) {
        v[i] = *(const float4*)(xr + i * 128 + lane * 4);
        s += v[i].x + v[i].y + v[i].z + v[i].w;
        sq += v[i].x * v[i].x + v[i].y * v[i].y + v[i].z * v[i].z + v[i].w * v[i].w;
    }
#pragma unroll
    for (int off = 16; off > 0; off >>= 1) {
        s += __shfl_xor_sync(0xffffffffu, s, off);
        sq += __shfl_xor_sync(0xffffffffu, sq, off);
    }
    float m = s * (1.f / DIMC);
    float rstd = rsqrtf(sq * (1.f / DIMC) - m * m + LNEPS);
    int b = row / NN;
    float mk = mask ? mask[row] : 1.f;
#pragma unroll
    for (int i = 0; i < 4; i++) {
        int c = i * 128 + lane * 4;
        float4 gg = *(const float4*)(g + c);
        float4 o;
        o.x = (v[i].x - m) * rstd * gg.x;
        o.y = (v[i].y - m) * rstd * gg.y;
        o.z = (v[i].z - m) * rstd * gg.z;
        o.w = (v[i].w - m) * rstd * gg.w;
        if (useMod) {
            const float* scp = scsh + b * 2 * DIMC + c;
            const float* shp = scp + DIMC;
            float4 sc = *(const float4*)scp, sh = *(const float4*)shp;
            o.x = o.x * (sc.x + 1.f) + sh.x;
            o.y = o.y * (sc.y + 1.f) + sh.y;
            o.z = o.z * (sc.z + 1.f) + sh.z;
            o.w = o.w * (sc.w + 1.f) + sh.w;
        }
        o.x = tf32r(o.x * mk);
        o.y = tf32r(o.y * mk);
        o.z = tf32r(o.z * mk);
        o.w = tf32r(o.w * mk);
        *(float4*)(out + (size_t)row * DIMC + c) = o;
    }
}

// ---------------- 128x128 3-stage tf32 GEMM (2 CTA/SM) ------------------------
#define ATILE 4608                 // 128*36 floats
#define BTILE 4352                 // 32*136 floats
#define STG_FLOATS (ATILE + BTILE) // 8960
#define TGEMM_SMEM (3 * STG_FLOATS * 4)

__device__ __forceinline__ void tgemm_body(
    const float* __restrict__ A, const float* __restrict__ Bm,
    float* __restrict__ C, int Ncols, int K,
    const float* __restrict__ bias, const float* __restrict__ residual,
    const float* __restrict__ rowmask, const float* __restrict__ mod,
    float alpha, int mode, int roundOut, int roundA,
    int rowBase, int colBase, float* sm) {
    uint32_t smB = smem_u32(sm);
    int t = threadIdx.x;
    int lane = t & 31, warp = t >> 5;
    int gid = lane >> 2, tig = lane & 3;
    int wr = warp >> 1, wc = warp & 1;

    const float* gA = A + (size_t)rowBase * K;
    const float* gB = Bm + colBase;

    float acc[2][8][4];
#pragma unroll
    for (int i = 0; i < 2; i++)
#pragma unroll
        for (int j = 0; j < 8; j++)
#pragma unroll
            for (int c = 0; c < 4; c++) acc[i][j][c] = 0.f;

    int T = K >> 5;

#define ISSUE_TILE(kt, st)                                                      \
    {                                                                           \
        int kk0 = (kt) << 5;                                                    \
        uint32_t base = smB + (st) * STG_FLOATS * 4;                            \
        _Pragma("unroll") for (int l = 0; l < 4; l++) {                         \
            int idx = t + 256 * l;                                              \
            int mm = idx >> 3, c4 = idx & 7;                                    \
            CPA16(base + (mm * 36 + c4 * 4) * 4,                                \
                  gA + (size_t)mm * K + kk0 + c4 * 4);                          \
        }                                                                       \
        _Pragma("unroll") for (int l = 0; l < 4; l++) {                         \
            int idx = t + 256 * l;                                              \
            int kk = idx >> 5, n4 = idx & 31;                                   \
            CPA16(base + (ATILE + kk * 136 + n4 * 4) * 4,                       \
                  gB + (size_t)(kk0 + kk) * Ncols + n4 * 4);                    \
        }                                                                       \
        CP_COMMIT();                                                            \
    }

    ISSUE_TILE(0, 0);
    ISSUE_TILE(1, 1);
    for (int it = 0; it < T; it++) {
        if (it < T - 1) { CP_WAIT(1); } else { CP_WAIT(0); }
        __syncthreads();
        if (it + 2 < T) ISSUE_TILE(it + 2, (it + 2) % 3);
        const float* Asb = sm + (it % 3) * STG_FLOATS;
        const float* Bsb = Asb + ATILE;
#pragma unroll
        for (int ks = 0; ks < 32; ks += 8) {
            uint32_t a[2][4];
#pragma unroll
            for (int mt = 0; mt < 2; mt++) {
                int m0 = wr * 32 + mt * 16;
                float f0 = Asb[(m0 + gid) * 36 + ks + tig];
                float f1 = Asb[(m0 + gid + 8) * 36 + ks + tig];
                float f2 = Asb[(m0 + gid) * 36 + ks + tig + 4];
                float f3 = Asb[(m0 + gid + 8) * 36 + ks + tig + 4];
                if (roundA) {
                    f0 = tf32r(f0); f1 = tf32r(f1);
                    f2 = tf32r(f2); f3 = tf32r(f3);
                }
                a[mt][0] = __float_as_uint(f0);
                a[mt][1] = __float_as_uint(f1);
                a[mt][2] = __float_as_uint(f2);
                a[mt][3] = __float_as_uint(f3);
            }
            uint32_t b[8][2];
#pragma unroll
            for (int nt = 0; nt < 8; nt++) {
                int n0 = wc * 64 + nt * 8;
                b[nt][0] = __float_as_uint(Bsb[(ks + tig) * 136 + n0 + gid]);
                b[nt][1] = __float_as_uint(Bsb[(ks + tig + 4) * 136 + n0 + gid]);
            }
#pragma unroll
            for (int mt = 0; mt < 2; mt++)
#pragma unroll
                for (int nt = 0; nt < 8; nt++)
                    MMA_TF32(acc[mt][nt], a[mt][0], a[mt][1], a[mt][2], a[mt][3],
                             b[nt][0], b[nt][1]);
        }
        __syncthreads();
    }
#undef ISSUE_TILE

#pragma unroll
    for (int mt = 0; mt < 2; mt++)
#pragma unroll
        for (int half = 0; half < 2; half++) {
            int i = rowBase + wr * 32 + mt * 16 + gid + half * 8;
            int b = i / NN;
            float rm = (mode >= 2) ? rowmask[i] : 1.f;
#pragma unroll
            for (int nt = 0; nt < 8; nt++) {
                int j = colBase + wc * 64 + nt * 8 + tig * 2;
                size_t off = (size_t)i * Ncols + j;
                float v0 = acc[mt][nt][half * 2 + 0] * alpha;
                float v1 = acc[mt][nt][half * 2 + 1] * alpha;
                if (mode == 0) {
                    if (bias) { v0 += bias[j]; v1 += bias[j + 1]; }
                } else if (mode == 1) {
                    v0 += bias[j];
                    v1 += bias[j + 1];
                    v0 = v0 / (1.f + __expf(-v0));
                    v1 = v1 / (1.f + __expf(-v1));
                    float sc0 = mod[b * 2 * Ncols + j], sc1 = mod[b * 2 * Ncols + j + 1];
                    float sh0 = mod[b * 2 * Ncols + Ncols + j];
                    float sh1 = mod[b * 2 * Ncols + Ncols + j + 1];
                    v0 = v0 * (sc0 + 1.f) + sh0;
                    v1 = v1 * (sc1 + 1.f) + sh1;
                } else if (mode == 2) {
                    float2 r = *(const float2*)(residual + off);
                    v0 = r.x + v0 * rm;
                    v1 = r.y + v1 * rm;
                } else {
                    float2 r = *(const float2*)(residual + off);
                    v0 = (r.x + v0 + bias[j]) * rm;
                    v1 = (r.y + v1 + bias[j + 1]) * rm;
                }
                if (roundOut) { v0 = tf32r(v0); v1 = tf32r(v1); }
                *(float2*)(C + off) = make_float2(v0, v1);
            }
        }
}

__global__ __launch_bounds__(256, 2)
void tgemm_k(const float* __restrict__ A, const float* __restrict__ Bm,
             float* __restrict__ C, int Ncols, int K,
             const float* __restrict__ bias, const float* __restrict__ residual,
             const float* __restrict__ rowmask, const float* __restrict__ mod,
             float alpha, int mode, int roundOut) {
    extern __shared__ float sm[];
    tgemm_body(A, Bm, C, Ncols, K, bias, residual, rowmask, mod, alpha, mode,
               roundOut, 0, blockIdx.y * 128, blockIdx.x * 128, sm);
}

// merged q + kv projection: blockIdx.x < 4 -> q tile, else kv tile
__global__ __launch_bounds__(256, 2)
void qkv_k(const float* __restrict__ xn, const float* __restrict__ x,
           const float* __restrict__ wq, const float* __restrict__ wkv,
           float* __restrict__ q, float* __restrict__ kv) {
    extern __shared__ float sm[];
    if (blockIdx.x < HIDD / 128) {
        tgemm_body(xn, wq, q, HIDD, DIMC, nullptr, nullptr, nullptr, nullptr,
                   SCALEQ, 0, 1, 0, blockIdx.y * 128, blockIdx.x * 128, sm);
    } else {
        tgemm_body(x, wkv, kv, 2 * HIDD, DIMC, nullptr, nullptr, nullptr, nullptr,
                   1.f, 0, 1, 1, blockIdx.y * 128,
                   (blockIdx.x - HIDD / 128) * 128, sm);
    }
}

// ---------------- 64x128 3-stage tf32 GEMM (M-split for sub-wave shapes) ------
// 128 threads, 4 warps of 32x64 (2x2). For wo/ffout (N=512): 256 CTAs, 2/SM.
#define A64TILE 2304                  // 64*36 floats
#define STG64 (A64TILE + BTILE)       // 6656 floats
#define TG64_SMEM (3 * STG64 * 4)     // 79,872 B

__global__ __launch_bounds__(128, 2)
void tgemm64_k(const float* __restrict__ A, const float* __restrict__ Bm,
               float* __restrict__ C, int Ncols, int K,
               const float* __restrict__ bias, const float* __restrict__ residual,
               const float* __restrict__ rowmask, float alpha, int mode) {
    extern __shared__ float sm[];
    uint32_t smB = smem_u32(sm);
    int t = threadIdx.x;
    int lane = t & 31, warp = t >> 5;
    int gid = lane >> 2, tig = lane & 3;
    int wr = warp >> 1, wc = warp & 1;
    int rowBase = blockIdx.y * 64, colBase = blockIdx.x * 128;

    const float* gA = A + (size_t)rowBase * K;
    const float* gB = Bm + colBase;

    float acc[2][8][4];
#pragma unroll
    for (int i = 0; i < 2; i++)
#pragma unroll
        for (int j = 0; j < 8; j++)
#pragma unroll
            for (int c = 0; c < 4; c++) acc[i][j][c] = 0.f;

    int T = K >> 5;

#define ISSUE64(kt, st)                                                         \
    {                                                                           \
        int kk0 = (kt) << 5;                                                    \
        uint32_t base = smB + (st) * STG64 * 4;                                 \
        _Pragma("unroll") for (int l = 0; l < 4; l++) {                         \
            int idx = t + 128 * l;                                              \
            int mm = idx >> 3, c4 = idx & 7;                                    \
            CPA16(base + (mm * 36 + c4 * 4) * 4,                                \
                  gA + (size_t)mm * K + kk0 + c4 * 4);                          \
        }                                                                       \
        _Pragma("unroll") for (int l = 0; l < 8; l++) {                         \
            int idx = t + 128 * l;                                              \
            int kk = idx >> 5, n4 = idx & 31;                                   \
            CPA16(base + (A64TILE + kk * 136 + n4 * 4) * 4,                     \
                  gB + (size_t)(kk0 + kk) * Ncols + n4 * 4);                    \
        }                                                                       \
        CP_COMMIT();                                                            \
    }

    ISSUE64(0, 0);
    ISSUE64(1, 1);
    for (int it = 0; it < T; it++) {
        if (it < T - 1) { CP_WAIT(1); } else { CP_WAIT(0); }
        __syncthreads();
        if (it + 2 < T) ISSUE64(it + 2, (it + 2) % 3);
        const float* Asb = sm + (it % 3) * STG64;
        const float* Bsb = Asb + A64TILE;
#pragma unroll
        for (int ks = 0; ks < 32; ks += 8) {
            uint32_t a[2][4];
#pragma unroll
            for (int mt = 0; mt < 2; mt++) {
                int m0 = wr * 32 + mt * 16;
                a[mt][0] = __float_as_uint(Asb[(m0 + gid) * 36 + ks + tig]);
                a[mt][1] = __float_as_uint(Asb[(m0 + gid + 8) * 36 + ks + tig]);
                a[mt][2] = __float_as_uint(Asb[(m0 + gid) * 36 + ks + tig + 4]);
                a[mt][3] = __float_as_uint(Asb[(m0 + gid + 8) * 36 + ks + tig + 4]);
            }
            uint32_t b[8][2];
#pragma unroll
            for (int nt = 0; nt < 8; nt++) {
                int n0 = wc * 64 + nt * 8;
                b[nt][0] = __float_as_uint(Bsb[(ks + tig) * 136 + n0 + gid]);
                b[nt][1] = __float_as_uint(Bsb[(ks + tig + 4) * 136 + n0 + gid]);
            }
#pragma unroll
            for (int mt = 0; mt < 2; mt++)
#pragma unroll
                for (int nt = 0; nt < 8; nt++)
                    MMA_TF32(acc[mt][nt], a[mt][0], a[mt][1], a[mt][2], a[mt][3],
                             b[nt][0], b[nt][1]);
        }
        __syncthreads();
    }
#undef ISSUE64

#pragma unroll
    for (int mt = 0; mt < 2; mt++)
#pragma unroll
        for (int half = 0; half < 2; half++) {
            int i = rowBase + wr * 32 + mt * 16 + gid + half * 8;
            float rm = rowmask[i];
#pragma unroll
            for (int nt = 0; nt < 8; nt++) {
                int j = colBase + wc * 64 + nt * 8 + tig * 2;
                size_t off = (size_t)i * Ncols + j;
                float v0 = acc[mt][nt][half * 2 + 0] * alpha;
                float v1 = acc[mt][nt][half * 2 + 1] * alpha;
                float2 r = *(const float2*)(residual + off);
                if (mode == 2) {
                    v0 = r.x + v0 * rm;
                    v1 = r.y + v1 * rm;
                } else {
                    v0 = (r.x + v0 + bias[j]) * rm;
                    v1 = (r.y + v1 + bias[j + 1]) * rm;
                }
                *(float2*)(C + off) = make_float2(v0, v1);
            }
        }
}

// ---------------- flash attention --------------------------------------------
#define QS_FLOATS (128 * 68)
#define KS_FLOATS (64 * 68)
#define VS_FLOATS (64 * 72)
#define FLASH_SMEM ((QS_FLOATS + KS_FLOATS + VS_FLOATS + 65 + 64 + 64 + 3) * 4)

__global__ __launch_bounds__(256, 2)
void flash_k(const float* __restrict__ q, const float* __restrict__ kv,
             const int* __restrict__ ri, const float* __restrict__ mask,
             const float* __restrict__ rw, const float* __restrict__ rb,
             float* __restrict__ ao) {
    extern __shared__ float sm[];
    float* Qs = sm;
    float* Ks = Qs + QS_FLOATS;
    float* Vs = Ks + KS_FLOATS;
    float* rws = Vs + VS_FLOATS;
    float* mjs = rws + 65;
    int* rji = (int*)(mjs + 64);

    int b = blockIdx.y / HEADS, h = blockIdx.y % HEADS;
    int i0 = blockIdx.x * 128;
    int t = threadIdx.x;
    int lane = t & 31, warp = t >> 5;
    int gid = lane >> 2, tig = lane & 3;

#pragma unroll
    for (int l = 0; l < 8; l++) {
        int idx = t + 256 * l;
        int r = idx >> 4, dv = idx & 15;
        *(float4*)&Qs[r * 68 + dv * 4] =
            *(const float4*)(q + (size_t)(b * NN + i0 + r) * HIDD + h * DH + dv * 4);
    }
    if (t < 65) rws[t] = rw[t * HEADS + h] + rb[h];
    __syncthreads();

    int row0 = i0 + warp * 16 + gid;
    int row1 = row0 + 8;
    int ri0 = ri[b * NN + row0], ri1 = ri[b * NN + row1];
    float mi0 = mask[b * NN + row0], mi1 = mask[b * NN + row1];

    float O[8][4];
#pragma unroll
    for (int nt = 0; nt < 8; nt++)
#pragma unroll
        for (int c = 0; c < 4; c++) O[nt][c] = 0.f;
    float m0 = -1e30f, m1 = -1e30f, l0 = 0.f, l1 = 0.f;

    for (int j0 = 0; j0 < NN; j0 += 64) {
#pragma unroll
        for (int l = 0; l < 4; l++) {
            int idx = t + 256 * l;
            int r = idx >> 4, dv = idx & 15;
            const float* base = kv + (size_t)(b * NN + j0 + r) * 2 * HIDD + h * DH;
            *(float4*)&Ks[r * 68 + dv * 4] = *(const float4*)(base + dv * 4);
            *(float4*)&Vs[r * 72 + dv * 4] = *(const float4*)(base + HIDD + dv * 4);
        }
        if (t < 64) {
            rji[t] = ri[b * NN + j0 + t];
            mjs[t] = mask[b * NN + j0 + t];
        }
        __syncthreads();

        float S[8][4];
#pragma unroll
        for (int nt = 0; nt < 8; nt++)
#pragma unroll
            for (int c = 0; c < 4; c++) S[nt][c] = 0.f;
#pragma unroll
        for (int ks = 0; ks < 64; ks += 8) {
            uint32_t a0 = __float_as_uint(Qs[(warp * 16 + gid) * 68 + ks + tig]);
            uint32_t a1 = __float_as_uint(Qs[(warp * 16 + gid + 8) * 68 + ks + tig]);
            uint32_t a2 = __float_as_uint(Qs[(warp * 16 + gid) * 68 + ks + tig + 4]);
            uint32_t a3 = __float_as_uint(Qs[(warp * 16 + gid + 8) * 68 + ks + tig + 4]);
#pragma unroll
            for (int nt = 0; nt < 8; nt++) {
                uint32_t b0 = __float_as_uint(Ks[(nt * 8 + gid) * 68 + ks + tig]);
                uint32_t b1 = __float_as_uint(Ks[(nt * 8 + gid) * 68 + ks + tig + 4]);
                MMA_TF32(S[nt], a0, a1, a2, a3, b0, b1);
            }
        }

#pragma unroll
        for (int nt = 0; nt < 8; nt++) {
            int jl0 = nt * 8 + 2 * tig, jl1 = jl0 + 1;
            int rj0 = rji[jl0], rj1 = rji[jl1];
            float mj0 = mjs[jl0], mj1 = mjs[jl1];
            int d00 = min(max(ri0 - rj0, -MAXREL), MAXREL) + MAXREL;
            int d01 = min(max(ri0 - rj1, -MAXREL), MAXREL) + MAXREL;
            int d10 = min(max(ri1 - rj0, -MAXREL), MAXREL) + MAXREL;
            int d11 = min(max(ri1 - rj1, -MAXREL), MAXREL) + MAXREL;
            S[nt][0] += rws[d00] - (1.f - mi0 * mj0) * 1e6f;
            S[nt][1] += rws[d01] - (1.f - mi0 * mj1) * 1e6f;
            S[nt][2] += rws[d10] - (1.f - mi1 * mj0) * 1e6f;
            S[nt][3] += rws[d11] - (1.f - mi1 * mj1) * 1e6f;
        }

        float mx0 = -1e30f, mx1 = -1e30f;
#pragma unroll
        for (int nt = 0; nt < 8; nt++) {
            mx0 = fmaxf(mx0, fmaxf(S[nt][0], S[nt][1]));
            mx1 = fmaxf(mx1, fmaxf(S[nt][2], S[nt][3]));
        }
        mx0 = fmaxf(mx0, __shfl_xor_sync(0xffffffffu, mx0, 1));
        mx0 = fmaxf(mx0, __shfl_xor_sync(0xffffffffu, mx0, 2));
        mx1 = fmaxf(mx1, __shfl_xor_sync(0xffffffffu, mx1, 1));
        mx1 = fmaxf(mx1, __shfl_xor_sync(0xffffffffu, mx1, 2));
        float m0n = fmaxf(m0, mx0), m1n = fmaxf(m1, mx1);
        float sc0 = __expf(m0 - m0n), sc1 = __expf(m1 - m1n);
        m0 = m0n; m1 = m1n;

        float sum0 = 0.f, sum1 = 0.f;
#pragma unroll
        for (int nt = 0; nt < 8; nt++) {
            S[nt][0] = __expf(S[nt][0] - m0n);
            S[nt][1] = __expf(S[nt][1] - m0n);
            S[nt][2] = __expf(S[nt][2] - m1n);
            S[nt][3] = __expf(S[nt][3] - m1n);
            sum0 += S[nt][0] + S[nt][1];
            sum1 += S[nt][2] + S[nt][3];
            S[nt][0] = tf32r(S[nt][0]);
            S[nt][1] = tf32r(S[nt][1]);
            S[nt][2] = tf32r(S[nt][2]);
            S[nt][3] = tf32r(S[nt][3]);
        }
        sum0 += __shfl_xor_sync(0xffffffffu, sum0, 1);
        sum0 += __shfl_xor_sync(0xffffffffu, sum0, 2);
        sum1 += __shfl_xor_sync(0xffffffffu, sum1, 1);
        sum1 += __shfl_xor_sync(0xffffffffu, sum1, 2);
        l0 = l0 * sc0 + sum0;
        l1 = l1 * sc1 + sum1;

#pragma unroll
        for (int nt = 0; nt < 8; nt++) {
            O[nt][0] *= sc0; O[nt][1] *= sc0;
            O[nt][2] *= sc1; O[nt][3] *= sc1;
        }

        int src1 = (lane & ~3) | (tig >> 1);
        int src2 = src1 + 2;
#pragma unroll
        for (int kt = 0; kt < 8; kt++) {
            float s0a = __shfl_sync(0xffffffffu, S[kt][0], src1);
            float s0b = __shfl_sync(0xffffffffu, S[kt][1], src1);
            float s2a = __shfl_sync(0xffffffffu, S[kt][0], src2);
            float s2b = __shfl_sync(0xffffffffu, S[kt][1], src2);
            float s1a = __shfl_sync(0xffffffffu, S[kt][2], src1);
            float s1b = __shfl_sync(0xffffffffu, S[kt][3], src1);
            float s3a = __shfl_sync(0xffffffffu, S[kt][2], src2);
            float s3b = __shfl_sync(0xffffffffu, S[kt][3], src2);
            uint32_t a0 = __float_as_uint((tig & 1) ? s0b : s0a);
            uint32_t a2 = __float_as_uint((tig & 1) ? s2b : s2a);
            uint32_t a1 = __float_as_uint((tig & 1) ? s1b : s1a);
            uint32_t a3 = __float_as_uint((tig & 1) ? s3b : s3a);
#pragma unroll
            for (int nt = 0; nt < 8; nt++) {
                uint32_t b0 = __float_as_uint(Vs[(kt * 8 + tig) * 72 + nt * 8 + gid]);
                uint32_t b1 = __float_as_uint(Vs[(kt * 8 + tig + 4) * 72 + nt * 8 + gid]);
                MMA_TF32(O[nt], a0, a1, a2, a3, b0, b1);
            }
        }
        __syncthreads();
    }

    float inv0 = 1.f / l0, inv1 = 1.f / l1;
#pragma unroll
    for (int nt = 0; nt < 8; nt++) {
        int dd = nt * 8 + tig * 2;
        *(float2*)(ao + (size_t)(b * NN + row0) * HIDD + h * DH + dd) =
            make_float2(tf32r(O[nt][0] * inv0), tf32r(O[nt][1] * inv0));
        *(float2*)(ao + (size_t)(b * NN + row1) * HIDD + h * DH + dd) =
            make_float2(tf32r(O[nt][2] * inv1), tf32r(O[nt][3] * inv1));
    }
}

// ---------------- launch -----------------------------------------------------
extern "C" void kernel_launch(void* const* d_in, const int* in_sizes, int n_in,
                              void* d_out, int out_size) {
    const float* x_in      = (const float*)d_in[0];
    const float* time_in   = (const float*)d_in[1];
    const float* seq_mask  = (const float*)d_in[2];
    const int*   res_idx   = (const int*)d_in[3];
    const float* relpos_w  = (const float*)d_in[4];
    const float* relpos_b  = (const float*)d_in[5];
    const float* attn_g    = (const float*)d_in[6];
    const float* attn_tw   = (const float*)d_in[7];
    const float* attn_tb   = (const float*)d_in[8];
    const float* to_q_w    = (const float*)d_in[9];
    const float* to_kv_w   = (const float*)d_in[10];
    const float* to_out_w  = (const float*)d_in[11];
    const float* ff_g      = (const float*)d_in[12];
    const float* ff_tw     = (const float*)d_in[13];
    const float* ff_tb     = (const float*)d_in[14];
    const float* ff_in_w   = (const float*)d_in[15];
    const float* ff_in_b   = (const float*)d_in[16];
    const float* ff_out_w  = (const float*)d_in[17];
    const float* ff_out_b  = (const float*)d_in[18];

    float *tact, *scsh_a, *scsh_f, *xn, *q, *kv, *ao, *hb;
    float *wq, *wkv, *wo, *wfi, *wfo;
    cudaGetSymbolAddress((void**)&tact, g_tact);
    cudaGetSymbolAddress((void**)&scsh_a, g_scsh_a);
    cudaGetSymbolAddress((void**)&scsh_f, g_scsh_f);
    cudaGetSymbolAddress((void**)&xn, g_xn);
    cudaGetSymbolAddress((void**)&q, g_q);
    cudaGetSymbolAddress((void**)&kv, g_kv);
    cudaGetSymbolAddress((void**)&ao, g_ao);
    cudaGetSymbolAddress((void**)&hb, g_hb);
    cudaGetSymbolAddress((void**)&wq, g_wq);
    cudaGetSymbolAddress((void**)&wkv, g_wkv);
    cudaGetSymbolAddress((void**)&wo, g_wo);
    cudaGetSymbolAddress((void**)&wfi, g_wfi);
    cudaGetSymbolAddress((void**)&wfo, g_wfo);

    cudaFuncSetAttribute(tgemm_k, cudaFuncAttributeMaxDynamicSharedMemorySize,
                         TGEMM_SMEM);
    cudaFuncSetAttribute(qkv_k, cudaFuncAttributeMaxDynamicSharedMemorySize,
                         TGEMM_SMEM);
    cudaFuncSetAttribute(tgemm64_k, cudaFuncAttributeMaxDynamicSharedMemorySize,
                         TG64_SMEM);
    cudaFuncSetAttribute(flash_k, cudaFuncAttributeMaxDynamicSharedMemorySize,
                         FLASH_SMEM);

    float* x = (float*)d_out;
    const int M = BB * NN;

    round_all_k<<<592, 256>>>(
        to_q_w, wq, DEPTHL * DIMC * HIDD / 4,
        to_kv_w, wkv, DEPTHL * DIMC * 2 * HIDD / 4,
        to_out_w, wo, DEPTHL * HIDD * DIMC / 4,
        ff_in_w, wfi, DEPTHL * DIMC * INNERC / 4,
        ff_out_w, wfo, DEPTHL * INNERC * DIMC / 4);

    init_x_k<<<(BB * NN * DIMC + 255) / 256, 256>>>(x_in, seq_mask, x);
    silu_time_k<<<(BB * TCDD + 255) / 256, 256>>>(time_in, tact);
    time_all_k<<<dim3((2 * DIMC + 2 * INNERC) / 64, BB, DEPTHL), 256>>>(
        tact, attn_tw, attn_tb, ff_tw, ff_tb, scsh_a, scsh_f);

    for (int d = 0; d < DEPTHL; d++) {
        // --- attention block ---
        ln_mod_k<<<M / 8, 256>>>(x, attn_g + d * DIMC,
                                 scsh_a + (size_t)d * BB * 2 * DIMC, seq_mask, xn, 1);
        qkv_k<<<dim3(HIDD / 128 + 2 * HIDD / 128, M / 128), 256, TGEMM_SMEM>>>(
            xn, x, wq + (size_t)d * DIMC * HIDD, wkv + (size_t)d * DIMC * 2 * HIDD,
            q, kv);
        flash_k<<<dim3(NN / 128, BB * HEADS), 256, FLASH_SMEM>>>(
            q, kv, res_idx, seq_mask, relpos_w, relpos_b, ao);
        tgemm64_k<<<dim3(DIMC / 128, M / 64), 128, TG64_SMEM>>>(
            ao, wo + (size_t)d * HIDD * DIMC, x, DIMC, HIDD,
            nullptr, x, seq_mask, 1.f, 2);

        // --- feed-forward block ---
        ln_mod_k<<<M / 8, 256>>>(x, ff_g + d * DIMC, nullptr, nullptr, xn, 0);
        tgemm_k<<<dim3(INNERC / 128, M / 128), 256, TGEMM_SMEM>>>(
            xn, wfi + (size_t)d * DIMC * INNERC, hb, INNERC, DIMC,
            ff_in_b + (size_t)d * INNERC, nullptr, nullptr,
            scsh_f + (size_t)d * BB * 2 * INNERC, 1.f, 1, 1);
        tgemm64_k<<<dim3(DIMC / 128, M / 64), 128, TG64_SMEM>>>(
            hb, wfo + (size_t)d * INNERC * DIMC, x, DIMC, INNERC,
            ff_out_b + (size_t)d * DIMC, x, seq_mask, 1.f, 3);
    }
}

// round 13
// speedup vs baseline: 1.4366x; 1.4366x over previous
#include <cuda_runtime.h>
#include <cuda_fp16.h>
#include <math.h>
#include <stdint.h>

#define BB     4
#define NN     1024
#define DIMC   512
#define DEPTHL 4
#define HEADS  8
#define DH     64
#define TCDD   512
#define HIDD   512
#define INNERC 2048
#define MAXREL 32
#define SCALEQ 0.125f
#define LNEPS  1e-5f

// ---------------- scratch ----------------------------------------------------
__device__ float  g_tact[BB * TCDD];
__device__ float  g_scsh_a[DEPTHL * BB * 2 * DIMC];
__device__ float  g_scsh_f[DEPTHL * BB * 2 * INNERC];
__device__ __half g_xn[BB * NN * DIMC];
__device__ __half g_xh[BB * NN * DIMC];
__device__ __half g_q[BB * NN * HIDD];
__device__ __half g_kv[BB * NN * 2 * HIDD];
__device__ __half g_ao[BB * NN * HIDD];
__device__ __half g_hb[BB * NN * INNERC];
// fp16 weights, transposed to [N][K]
__device__ __half g_wq[DEPTHL * DIMC * HIDD];
__device__ __half g_wkv[DEPTHL * DIMC * 2 * HIDD];
__device__ __half g_wo[DEPTHL * HIDD * DIMC];
__device__ __half g_wfi[DEPTHL * DIMC * INNERC];
__device__ __half g_wfo[DEPTHL * INNERC * DIMC];

// ---------------- helpers ----------------------------------------------------
#define MMA_F16(c, a0, a1, a2, a3, b0, b1)                                      \
    asm volatile(                                                               \
        "mma.sync.aligned.m16n8k16.row.col.f32.f16.f16.f32 "                    \
        "{%0,%1,%2,%3},{%4,%5,%6,%7},{%8,%9},{%0,%1,%2,%3};"                    \
        : "+f"(c[0]), "+f"(c[1]), "+f"(c[2]), "+f"(c[3])                        \
        : "r"(a0), "r"(a1), "r"(a2), "r"(a3), "r"(b0), "r"(b1))

#define CPA16(dst, src)                                                         \
    asm volatile("cp.async.cg.shared.global [%0], [%1], 16;" ::"r"(dst), "l"(src))
#define CP_COMMIT() asm volatile("cp.async.commit_group;")
#define CP_WAIT(n)  asm volatile("cp.async.wait_group %0;" ::"n"(n))

__device__ __forceinline__ uint32_t smem_u32(const void* p) {
    return (uint32_t)__cvta_generic_to_shared(p);
}
__device__ __forceinline__ uint32_t ld32h(const __half* p) {
    return *(const uint32_t*)p;
}
__device__ __forceinline__ uint32_t packh2(float lo, float hi) {
    __half2 h = __floats2half2_rn(lo, hi);
    return *(uint32_t*)&h;
}

// ---------------- weight round+transpose: [D][K][N] f32 -> [D][N][K] f16 -----
__global__ void transpose_h_k(const float* __restrict__ in, __half* __restrict__ out,
                              int K, int N) {
    __shared__ float tile[32][33];
    int d = blockIdx.z;
    int n0 = blockIdx.x * 32, k0 = blockIdx.y * 32;
    int tn = threadIdx.x & 31, tk = threadIdx.x >> 5;
    const float* inp = in + ((size_t)d * K + k0) * N + n0;
#pragma unroll
    for (int i = 0; i < 4; i++)
        tile[tk + 8 * i][tn] = inp[(size_t)(tk + 8 * i) * N + tn];
    __syncthreads();
    __half* op = out + ((size_t)d * N + n0) * K + k0;
#pragma unroll
    for (int i = 0; i < 4; i++)
        op[(size_t)(tk + 8 * i) * K + tn] = __float2half_rn(tile[tn][tk + 8 * i]);
}

__global__ void silu_time_k(const float* __restrict__ tm, float* __restrict__ out) {
    int i = blockIdx.x * 256 + threadIdx.x;
    if (i < BB * TCDD) {
        float v = tm[i];
        out[i] = v / (1.f + __expf(-v));
    }
}

__global__ void init_x_k(const float* __restrict__ xin, const float* __restrict__ mask,
                         float* __restrict__ x) {
    int i = blockIdx.x * 256 + threadIdx.x;
    if (i < BB * NN * DIMC) x[i] = xin[i] * mask[i / DIMC];
}

// all layers' time-conditioning GEMVs (fp32, unchanged)
__global__ __launch_bounds__(256)
void time_all_k(const float* __restrict__ tact,
                const float* __restrict__ atw, const float* __restrict__ atb,
                const float* __restrict__ ftw, const float* __restrict__ ftb,
                float* __restrict__ scsh_a, float* __restrict__ scsh_f) {
    __shared__ float red[4][64];
    int colL = threadIdx.x & 63, kg = threadIdx.x >> 6;
    int col = blockIdx.x * 64 + colL;
    int b = blockIdx.y, d = blockIdx.z;
    const float* t = tact + b * TCDD + kg * 128;
    const float* W;
    const float* bias;
    float* out;
    int Ncols, c;
    if (col < 2 * DIMC) {
        Ncols = 2 * DIMC;
        c = col;
        W = atw + (size_t)d * TCDD * Ncols;
        bias = atb + (size_t)d * Ncols;
        out = scsh_a + ((size_t)d * BB + b) * Ncols;
    } else {
        Ncols = 2 * INNERC;
        c = col - 2 * DIMC;
        W = ftw + (size_t)d * TCDD * Ncols;
        bias = ftb + (size_t)d * Ncols;
        out = scsh_f + ((size_t)d * BB + b) * Ncols;
    }
    const float* Wp = W + (size_t)(kg * 128) * Ncols + c;
    float a0 = 0.f, a1 = 0.f;
#pragma unroll 4
    for (int k = 0; k < 128; k += 2) {
        a0 += t[k] * Wp[(size_t)k * Ncols];
        a1 += t[k + 1] * Wp[(size_t)(k + 1) * Ncols];
    }
    red[kg][colL] = a0 + a1;
    __syncthreads();
    if (kg == 0)
        out[c] = red[0][colL] + red[1][colL] + red[2][colL] + red[3][colL] + bias[c];
}

// Warp-per-row LayerNorm (+AdaLN mod, +row mask); fp16 outputs.
__global__ __launch_bounds__(256)
void ln_mod_k(const float* __restrict__ x, const float* __restrict__ g,
              const float* __restrict__ scsh, const float* __restrict__ mask,
              __half* __restrict__ out, __half* __restrict__ out2, int useMod) {
    int warp = threadIdx.x >> 5, lane = threadIdx.x & 31;
    int row = blockIdx.x * 8 + warp;
    const float* xr = x + (size_t)row * DIMC;
    float4 v[4];
    float s = 0.f, sq = 0.f;
#pragma unroll
    for (int i = 0; i < 4; i++) {
        v[i] = *(const float4*)(xr + i * 128 + lane * 4);
        s += v[i].x + v[i].y + v[i].z + v[i].w;
        sq += v[i].x * v[i].x + v[i].y * v[i].y + v[i].z * v[i].z + v[i].w * v[i].w;
    }
#pragma unroll
    for (int off = 16; off > 0; off >>= 1) {
        s += __shfl_xor_sync(0xffffffffu, s, off);
        sq += __shfl_xor_sync(0xffffffffu, sq, off);
    }
    float m = s * (1.f / DIMC);
    float rstd = rsqrtf(sq * (1.f / DIMC) - m * m + LNEPS);
    int b = row / NN;
    float mk = mask ? mask[row] : 1.f;
#pragma unroll
    for (int i = 0; i < 4; i++) {
        int c = i * 128 + lane * 4;
        float4 gg = *(const float4*)(g + c);
        float4 o;
        o.x = (v[i].x - m) * rstd * gg.x;
        o.y = (v[i].y - m) * rstd * gg.y;
        o.z = (v[i].z - m) * rstd * gg.z;
        o.w = (v[i].w - m) * rstd * gg.w;
        if (useMod) {
            const float* scp = scsh + b * 2 * DIMC + c;
            const float* shp = scp + DIMC;
            float4 sc = *(const float4*)scp, sh = *(const float4*)shp;
            o.x = o.x * (sc.x + 1.f) + sh.x;
            o.y = o.y * (sc.y + 1.f) + sh.y;
            o.z = o.z * (sc.z + 1.f) + sh.z;
            o.w = o.w * (sc.w + 1.f) + sh.w;
        }
        uint2 pk;
        pk.x = packh2(o.x * mk, o.y * mk);
        pk.y = packh2(o.z * mk, o.w * mk);
        *(uint2*)(out + (size_t)row * DIMC + c) = pk;
        if (out2) {
            uint2 p2;
            p2.x = packh2(v[i].x, v[i].y);
            p2.y = packh2(v[i].z, v[i].w);
            *(uint2*)(out2 + (size_t)row * DIMC + c) = p2;
        }
    }
}

// ---------------- fp16 128x128 3-stage GEMM ----------------------------------
// A [M][K] f16; Bt [N][K] f16 (pre-transposed). k-tile 32 (two k16 steps).
// smem rows: 40 halves stride (80B; 20-bank step -> conflict-free frag loads).
#define AH_TILE 5120               // 128*40 halves
#define HSTG_BYTES 20480           // (A + B) * 2 bytes
#define HG_SMEM (3 * HSTG_BYTES)

__device__ __forceinline__ void hgemm_body(
    const __half* __restrict__ A, const __half* __restrict__ Bt,
    void* __restrict__ Cv, int Ncols, int K,
    const float* __restrict__ bias, const float* __restrict__ residual,
    const float* __restrict__ rowmask, const float* __restrict__ mod,
    float alpha, int mode, int rowBase, int colBase, char* smraw) {
    uint32_t smB = smem_u32(smraw);
    int t = threadIdx.x;
    int lane = t & 31, warp = t >> 5;
    int gid = lane >> 2, tig = lane & 3;
    int wr = warp >> 1, wc = warp & 1;

    const __half* gA = A + (size_t)rowBase * K;
    const __half* gB = Bt + (size_t)colBase * K;

    float acc[2][8][4];
#pragma unroll
    for (int i = 0; i < 2; i++)
#pragma unroll
        for (int j = 0; j < 8; j++)
#pragma unroll
            for (int c = 0; c < 4; c++) acc[i][j][c] = 0.f;

    int T = K >> 5;

#define H_ISSUE(kt, st)                                                         \
    {                                                                           \
        int kk0 = (kt) << 5;                                                    \
        uint32_t base = smB + (st) * HSTG_BYTES;                                \
        _Pragma("unroll") for (int l = 0; l < 2; l++) {                         \
            int idx = t + 256 * l;                                              \
            int rr = idx >> 2, c4 = idx & 3;                                    \
            CPA16(base + rr * 80 + c4 * 16,                                     \
                  gA + (size_t)rr * K + kk0 + c4 * 8);                          \
        }                                                                       \
        _Pragma("unroll") for (int l = 0; l < 2; l++) {                         \
            int idx = t + 256 * l;                                              \
            int rr = idx >> 2, c4 = idx & 3;                                    \
            CPA16(base + 10240 + rr * 80 + c4 * 16,                             \
                  gB + (size_t)rr * K + kk0 + c4 * 8);                          \
        }                                                                       \
        CP_COMMIT();                                                            \
    }

    H_ISSUE(0, 0);
    H_ISSUE(1, 1);
    for (int it = 0; it < T; it++) {
        if (it < T - 1) { CP_WAIT(1); } else { CP_WAIT(0); }
        __syncthreads();
        if (it + 2 < T) H_ISSUE(it + 2, (it + 2) % 3);
        const __half* Asb = (const __half*)(smraw + (it % 3) * HSTG_BYTES);
        const __half* Bsb = Asb + AH_TILE;
#pragma unroll
        for (int ks = 0; ks < 32; ks += 16) {
            uint32_t a[2][4];
#pragma unroll
            for (int mt = 0; mt < 2; mt++) {
                int m0 = wr * 32 + mt * 16;
                a[mt][0] = ld32h(&Asb[(m0 + gid) * 40 + ks + 2 * tig]);
                a[mt][1] = ld32h(&Asb[(m0 + gid + 8) * 40 + ks + 2 * tig]);
                a[mt][2] = ld32h(&Asb[(m0 + gid) * 40 + ks + 2 * tig + 8]);
                a[mt][3] = ld32h(&Asb[(m0 + gid + 8) * 40 + ks + 2 * tig + 8]);
            }
            uint32_t b[8][2];
#pragma unroll
            for (int nt = 0; nt < 8; nt++) {
                int n0 = wc * 64 + nt * 8;
                b[nt][0] = ld32h(&Bsb[(n0 + gid) * 40 + ks + 2 * tig]);
                b[nt][1] = ld32h(&Bsb[(n0 + gid) * 40 + ks + 2 * tig + 8]);
            }
#pragma unroll
            for (int mt = 0; mt < 2; mt++)
#pragma unroll
                for (int nt = 0; nt < 8; nt++)
                    MMA_F16(acc[mt][nt], a[mt][0], a[mt][1], a[mt][2], a[mt][3],
                            b[nt][0], b[nt][1]);
        }
        __syncthreads();
    }
#undef H_ISSUE

#pragma unroll
    for (int mt = 0; mt < 2; mt++)
#pragma unroll
        for (int half = 0; half < 2; half++) {
            int i = rowBase + wr * 32 + mt * 16 + gid + half * 8;
            int b = i / NN;
            float rm = (mode >= 2) ? rowmask[i] : 1.f;
#pragma unroll
            for (int nt = 0; nt < 8; nt++) {
                int j = colBase + wc * 64 + nt * 8 + tig * 2;
                size_t off = (size_t)i * Ncols + j;
                float v0 = acc[mt][nt][half * 2 + 0] * alpha;
                float v1 = acc[mt][nt][half * 2 + 1] * alpha;
                if (mode == 0) {
                    *(uint32_t*)((__half*)Cv + off) = packh2(v0, v1);
                } else if (mode == 1) {
                    v0 += bias[j];
                    v1 += bias[j + 1];
                    v0 = v0 / (1.f + __expf(-v0));
                    v1 = v1 / (1.f + __expf(-v1));
                    float sc0 = mod[b * 2 * Ncols + j], sc1 = mod[b * 2 * Ncols + j + 1];
                    float sh0 = mod[b * 2 * Ncols + Ncols + j];
                    float sh1 = mod[b * 2 * Ncols + Ncols + j + 1];
                    v0 = v0 * (sc0 + 1.f) + sh0;
                    v1 = v1 * (sc1 + 1.f) + sh1;
                    *(uint32_t*)((__half*)Cv + off) = packh2(v0, v1);
                } else if (mode == 2) {
                    float2 r = *(const float2*)(residual + off);
                    *(float2*)((float*)Cv + off) =
                        make_float2(r.x + v0 * rm, r.y + v1 * rm);
                } else {
                    float2 r = *(const float2*)(residual + off);
                    *(float2*)((float*)Cv + off) =
                        make_float2((r.x + v0 + bias[j]) * rm,
                                    (r.y + v1 + bias[j + 1]) * rm);
                }
            }
        }
}

__global__ __launch_bounds__(256, 2)
void hgemm_k(const __half* __restrict__ A, const __half* __restrict__ Bt,
             void* __restrict__ C, int Ncols, int K,
             const float* __restrict__ bias, const float* __restrict__ residual,
             const float* __restrict__ rowmask, const float* __restrict__ mod,
             float alpha, int mode) {
    extern __shared__ char smraw[];
    hgemm_body(A, Bt, C, Ncols, K, bias, residual, rowmask, mod, alpha, mode,
               blockIdx.y * 128, blockIdx.x * 128, smraw);
}

// merged q + kv: blockIdx.x < 4 -> q, else kv
__global__ __launch_bounds__(256, 2)
void qkv_k(const __half* __restrict__ xn, const __half* __restrict__ xh,
           const __half* __restrict__ wq, const __half* __restrict__ wkv,
           __half* __restrict__ q, __half* __restrict__ kv) {
    extern __shared__ char smraw[];
    if (blockIdx.x < HIDD / 128) {
        hgemm_body(xn, wq, q, HIDD, DIMC, nullptr, nullptr, nullptr, nullptr,
                   SCALEQ, 0, blockIdx.y * 128, blockIdx.x * 128, smraw);
    } else {
        hgemm_body(xh, wkv, kv, 2 * HIDD, DIMC, nullptr, nullptr, nullptr, nullptr,
                   1.f, 0, blockIdx.y * 128, (blockIdx.x - HIDD / 128) * 128, smraw);
    }
}

// ---------------- fp16 flash attention ---------------------------------------
// Qs [i][d] 128x72h, Ks [j][d] 64x72h, Vs [d][j] 64x72h (transposed).
#define QS_H (128 * 72)
#define KS_H (64 * 72)
#define VS_H (64 * 72)
#define FLASH_SMEM ((QS_H + KS_H + VS_H) * 2 + (65 + 64 + 64) * 4 + 16)

__global__ __launch_bounds__(256, 2)
void flash_k(const __half* __restrict__ q, const __half* __restrict__ kv,
             const int* __restrict__ ri, const float* __restrict__ mask,
             const float* __restrict__ rw, const float* __restrict__ rb,
             __half* __restrict__ ao) {
    extern __shared__ char smraw[];
    __half* Qs = (__half*)smraw;
    __half* Ks = Qs + QS_H;
    __half* Vs = Ks + KS_H;
    float* rws = (float*)(Vs + VS_H);
    float* mjs = rws + 65;
    int* rji = (int*)(mjs + 64);

    int b = blockIdx.y / HEADS, h = blockIdx.y % HEADS;
    int i0 = blockIdx.x * 128;
    int t = threadIdx.x;
    int lane = t & 31, warp = t >> 5;
    int gid = lane >> 2, tig = lane & 3;

    // Q fill: 128 rows x 64 halves; uint2 = 4 halves
#pragma unroll
    for (int l = 0; l < 8; l++) {
        int idx = t + 256 * l;
        int r = idx >> 4, dv = idx & 15;
        *(uint2*)&Qs[r * 72 + dv * 4] =
            *(const uint2*)(q + (size_t)(b * NN + i0 + r) * HIDD + h * DH + dv * 4);
    }
    if (t < 65) rws[t] = rw[t * HEADS + h] + rb[h];
    __syncthreads();

    int row0 = i0 + warp * 16 + gid;
    int row1 = row0 + 8;
    int ri0 = ri[b * NN + row0], ri1 = ri[b * NN + row1];
    float mi0 = mask[b * NN + row0], mi1 = mask[b * NN + row1];

    float O[8][4];
#pragma unroll
    for (int nt = 0; nt < 8; nt++)
#pragma unroll
        for (int c = 0; c < 4; c++) O[nt][c] = 0.f;
    float m0 = -1e30f, m1 = -1e30f, l0 = 0.f, l1 = 0.f;

    for (int j0 = 0; j0 < NN; j0 += 64) {
        // K fill: 64 rows x 64 halves
#pragma unroll
        for (int l = 0; l < 4; l++) {
            int idx = t + 256 * l;
            int r = idx >> 4, dv = idx & 15;
            *(uint2*)&Ks[r * 72 + dv * 4] =
                *(const uint2*)(kv + (size_t)(b * NN + j0 + r) * 2 * HIDD + h * DH +
                                dv * 4);
        }
        // V fill (transpose to [d][j]): thread: j = t&63, dgroup = t>>6 (16 d's)
        {
            int j = t & 63, dg = t >> 6;
            const __half* vsrc = kv + ((size_t)(b * NN + j0 + j) * 2 + 1) * HIDD +
                                 h * DH + dg * 16;
            __half tmp[16];
            *(uint4*)tmp = *(const uint4*)vsrc;
            *(uint4*)(tmp + 8) = *(const uint4*)(vsrc + 8);
#pragma unroll
            for (int i = 0; i < 16; i++) Vs[(dg * 16 + i) * 72 + j] = tmp[i];
        }
        if (t < 64) {
            rji[t] = ri[b * NN + j0 + t];
            mjs[t] = mask[b * NN + j0 + t];
        }
        __syncthreads();

        // S = Q K^T (4 k16 steps over d)
        float S[8][4];
#pragma unroll
        for (int nt = 0; nt < 8; nt++)
#pragma unroll
            for (int c = 0; c < 4; c++) S[nt][c] = 0.f;
#pragma unroll
        for (int kt = 0; kt < 4; kt++) {
            int ks = kt * 16;
            uint32_t a0 = ld32h(&Qs[(warp * 16 + gid) * 72 + ks + 2 * tig]);
            uint32_t a1 = ld32h(&Qs[(warp * 16 + gid + 8) * 72 + ks + 2 * tig]);
            uint32_t a2 = ld32h(&Qs[(warp * 16 + gid) * 72 + ks + 2 * tig + 8]);
            uint32_t a3 = ld32h(&Qs[(warp * 16 + gid + 8) * 72 + ks + 2 * tig + 8]);
#pragma unroll
            for (int nt = 0; nt < 8; nt++) {
                uint32_t b0 = ld32h(&Ks[(nt * 8 + gid) * 72 + ks + 2 * tig]);
                uint32_t b1 = ld32h(&Ks[(nt * 8 + gid) * 72 + ks + 2 * tig + 8]);
                MMA_F16(S[nt], a0, a1, a2, a3, b0, b1);
            }
        }

        // bias + mask
#pragma unroll
        for (int nt = 0; nt < 8; nt++) {
            int jl0 = nt * 8 + 2 * tig, jl1 = jl0 + 1;
            int rj0 = rji[jl0], rj1 = rji[jl1];
            float mj0 = mjs[jl0], mj1 = mjs[jl1];
            int d00 = min(max(ri0 - rj0, -MAXREL), MAXREL) + MAXREL;
            int d01 = min(max(ri0 - rj1, -MAXREL), MAXREL) + MAXREL;
            int d10 = min(max(ri1 - rj0, -MAXREL), MAXREL) + MAXREL;
            int d11 = min(max(ri1 - rj1, -MAXREL), MAXREL) + MAXREL;
            S[nt][0] += rws[d00] - (1.f - mi0 * mj0) * 1e6f;
            S[nt][1] += rws[d01] - (1.f - mi0 * mj1) * 1e6f;
            S[nt][2] += rws[d10] - (1.f - mi1 * mj0) * 1e6f;
            S[nt][3] += rws[d11] - (1.f - mi1 * mj1) * 1e6f;
        }

        float mx0 = -1e30f, mx1 = -1e30f;
#pragma unroll
        for (int nt = 0; nt < 8; nt++) {
            mx0 = fmaxf(mx0, fmaxf(S[nt][0], S[nt][1]));
            mx1 = fmaxf(mx1, fmaxf(S[nt][2], S[nt][3]));
        }
        mx0 = fmaxf(mx0, __shfl_xor_sync(0xffffffffu, mx0, 1));
        mx0 = fmaxf(mx0, __shfl_xor_sync(0xffffffffu, mx0, 2));
        mx1 = fmaxf(mx1, __shfl_xor_sync(0xffffffffu, mx1, 1));
        mx1 = fmaxf(mx1, __shfl_xor_sync(0xffffffffu, mx1, 2));
        float m0n = fmaxf(m0, mx0), m1n = fmaxf(m1, mx1);
        float sc0 = __expf(m0 - m0n), sc1 = __expf(m1 - m1n);
        m0 = m0n; m1 = m1n;

        float sum0 = 0.f, sum1 = 0.f;
#pragma unroll
        for (int nt = 0; nt < 8; nt++) {
            S[nt][0] = __expf(S[nt][0] - m0n);
            S[nt][1] = __expf(S[nt][1] - m0n);
            S[nt][2] = __expf(S[nt][2] - m1n);
            S[nt][3] = __expf(S[nt][3] - m1n);
            sum0 += S[nt][0] + S[nt][1];
            sum1 += S[nt][2] + S[nt][3];
        }
        sum0 += __shfl_xor_sync(0xffffffffu, sum0, 1);
        sum0 += __shfl_xor_sync(0xffffffffu, sum0, 2);
        sum1 += __shfl_xor_sync(0xffffffffu, sum1, 1);
        sum1 += __shfl_xor_sync(0xffffffffu, sum1, 2);
        l0 = l0 * sc0 + sum0;
        l1 = l1 * sc1 + sum1;

#pragma unroll
        for (int nt = 0; nt < 8; nt++) {
            O[nt][0] *= sc0; O[nt][1] *= sc0;
            O[nt][2] *= sc1; O[nt][3] *= sc1;
        }

        // O += P V : fp16 A-frags from S (free repack: col pairs = C-frag pairs)
#pragma unroll
        for (int kt = 0; kt < 4; kt++) {
            uint32_t a0 = packh2(S[2 * kt][0], S[2 * kt][1]);
            uint32_t a1 = packh2(S[2 * kt][2], S[2 * kt][3]);
            uint32_t a2 = packh2(S[2 * kt + 1][0], S[2 * kt + 1][1]);
            uint32_t a3 = packh2(S[2 * kt + 1][2], S[2 * kt + 1][3]);
#pragma unroll
            for (int nt = 0; nt < 8; nt++) {
                uint32_t b0 = ld32h(&Vs[(nt * 8 + gid) * 72 + kt * 16 + 2 * tig]);
                uint32_t b1 = ld32h(&Vs[(nt * 8 + gid) * 72 + kt * 16 + 2 * tig + 8]);
                MMA_F16(O[nt], a0, a1, a2, a3, b0, b1);
            }
        }
        __syncthreads();
    }

    float inv0 = 1.f / l0, inv1 = 1.f / l1;
#pragma unroll
    for (int nt = 0; nt < 8; nt++) {
        int dd = nt * 8 + tig * 2;
        *(uint32_t*)(ao + (size_t)(b * NN + row0) * HIDD + h * DH + dd) =
            packh2(O[nt][0] * inv0, O[nt][1] * inv0);
        *(uint32_t*)(ao + (size_t)(b * NN + row1) * HIDD + h * DH + dd) =
            packh2(O[nt][2] * inv1, O[nt][3] * inv1);
    }
}

// ---------------- launch -----------------------------------------------------
extern "C" void kernel_launch(void* const* d_in, const int* in_sizes, int n_in,
                              void* d_out, int out_size) {
    const float* x_in      = (const float*)d_in[0];
    const float* time_in   = (const float*)d_in[1];
    const float* seq_mask  = (const float*)d_in[2];
    const int*   res_idx   = (const int*)d_in[3];
    const float* relpos_w  = (const float*)d_in[4];
    const float* relpos_b  = (const float*)d_in[5];
    const float* attn_g    = (const float*)d_in[6];
    const float* attn_tw   = (const float*)d_in[7];
    const float* attn_tb   = (const float*)d_in[8];
    const float* to_q_w    = (const float*)d_in[9];
    const float* to_kv_w   = (const float*)d_in[10];
    const float* to_out_w  = (const float*)d_in[11];
    const float* ff_g      = (const float*)d_in[12];
    const float* ff_tw     = (const float*)d_in[13];
    const float* ff_tb     = (const float*)d_in[14];
    const float* ff_in_w   = (const float*)d_in[15];
    const float* ff_in_b   = (const float*)d_in[16];
    const float* ff_out_w  = (const float*)d_in[17];
    const float* ff_out_b  = (const float*)d_in[18];

    float *tact, *scsh_a, *scsh_f;
    __half *xn, *xh, *q, *kv, *ao, *hb, *wq, *wkv, *wo, *wfi, *wfo;
    cudaGetSymbolAddress((void**)&tact, g_tact);
    cudaGetSymbolAddress((void**)&scsh_a, g_scsh_a);
    cudaGetSymbolAddress((void**)&scsh_f, g_scsh_f);
    cudaGetSymbolAddress((void**)&xn, g_xn);
    cudaGetSymbolAddress((void**)&xh, g_xh);
    cudaGetSymbolAddress((void**)&q, g_q);
    cudaGetSymbolAddress((void**)&kv, g_kv);
    cudaGetSymbolAddress((void**)&ao, g_ao);
    cudaGetSymbolAddress((void**)&hb, g_hb);
    cudaGetSymbolAddress((void**)&wq, g_wq);
    cudaGetSymbolAddress((void**)&wkv, g_wkv);
    cudaGetSymbolAddress((void**)&wo, g_wo);
    cudaGetSymbolAddress((void**)&wfi, g_wfi);
    cudaGetSymbolAddress((void**)&wfo, g_wfo);

    cudaFuncSetAttribute(hgemm_k, cudaFuncAttributeMaxDynamicSharedMemorySize,
                         HG_SMEM);
    cudaFuncSetAttribute(qkv_k, cudaFuncAttributeMaxDynamicSharedMemorySize,
                         HG_SMEM);
    cudaFuncSetAttribute(flash_k, cudaFuncAttributeMaxDynamicSharedMemorySize,
                         FLASH_SMEM);

    float* x = (float*)d_out;
    const int M = BB * NN;

    // fp16 round + transpose all weights to [N][K]
    transpose_h_k<<<dim3(HIDD / 32, DIMC / 32, DEPTHL), 256>>>(to_q_w, wq, DIMC, HIDD);
    transpose_h_k<<<dim3(2 * HIDD / 32, DIMC / 32, DEPTHL), 256>>>(to_kv_w, wkv, DIMC,
                                                                   2 * HIDD);
    transpose_h_k<<<dim3(DIMC / 32, HIDD / 32, DEPTHL), 256>>>(to_out_w, wo, HIDD, DIMC);
    transpose_h_k<<<dim3(INNERC / 32, DIMC / 32, DEPTHL), 256>>>(ff_in_w, wfi, DIMC,
                                                                 INNERC);
    transpose_h_k<<<dim3(DIMC / 32, INNERC / 32, DEPTHL), 256>>>(ff_out_w, wfo, INNERC,
                                                                 DIMC);

    init_x_k<<<(BB * NN * DIMC + 255) / 256, 256>>>(x_in, seq_mask, x);
    silu_time_k<<<(BB * TCDD + 255) / 256, 256>>>(time_in, tact);
    time_all_k<<<dim3((2 * DIMC + 2 * INNERC) / 64, BB, DEPTHL), 256>>>(
        tact, attn_tw, attn_tb, ff_tw, ff_tb, scsh_a, scsh_f);

    for (int d = 0; d < DEPTHL; d++) {
        // --- attention block ---
        ln_mod_k<<<M / 8, 256>>>(x, attn_g + d * DIMC,
                                 scsh_a + (size_t)d * BB * 2 * DIMC, seq_mask,
                                 xn, xh, 1);
        qkv_k<<<dim3(12, M / 128), 256, HG_SMEM>>>(
            xn, xh, wq + (size_t)d * DIMC * HIDD, wkv + (size_t)d * DIMC * 2 * HIDD,
            q, kv);
        flash_k<<<dim3(NN / 128, BB * HEADS), 256, FLASH_SMEM>>>(
            q, kv, res_idx, seq_mask, relpos_w, relpos_b, ao);
        hgemm_k<<<dim3(DIMC / 128, M / 128), 256, HG_SMEM>>>(
            ao, wo + (size_t)d * HIDD * DIMC, x, DIMC, HIDD,
            nullptr, x, seq_mask, nullptr, 1.f, 2);

        // --- feed-forward block ---
        ln_mod_k<<<M / 8, 256>>>(x, ff_g + d * DIMC, nullptr, nullptr, xn, nullptr, 0);
        hgemm_k<<<dim3(INNERC / 128, M / 128), 256, HG_SMEM>>>(
            xn, wfi + (size_t)d * DIMC * INNERC, hb, INNERC, DIMC,
            ff_in_b + (size_t)d * INNERC, nullptr, nullptr,
            scsh_f + (size_t)d * BB * 2 * INNERC, 1.f, 1);
        hgemm_k<<<dim3(DIMC / 128, M / 128), 256, HG_SMEM>>>(
            hb, wfo + (size_t)d * INNERC * DIMC, x, DIMC, INNERC,
            ff_out_b + (size_t)d * DIMC, x, seq_mask, nullptr, 1.f, 3);
    }
}

// round 14
// speedup vs baseline: 1.5910x; 1.1075x over previous
#include <cuda_runtime.h>
#include <cuda_fp16.h>
#include <math.h>
#include <stdint.h>

#define BB     4
#define NN     1024
#define DIMC   512
#define DEPTHL 4
#define HEADS  8
#define DH     64
#define TCDD   512
#define HIDD   512
#define INNERC 2048
#define MAXREL 32
#define SCALEQ 0.125f
#define LNEPS  1e-5f

// ---------------- scratch ----------------------------------------------------
__device__ float  g_tact[BB * TCDD];
__device__ float  g_scsh_a[DEPTHL * BB * 2 * DIMC];
__device__ float  g_scsh_f[DEPTHL * BB * 2 * INNERC];
__device__ __half g_xn[BB * NN * DIMC];
__device__ __half g_xh[BB * NN * DIMC];
__device__ __half g_q[BB * NN * HIDD];
__device__ __half g_kv[BB * NN * 2 * HIDD];
__device__ __half g_ao[BB * NN * HIDD];
__device__ __half g_hb[BB * NN * INNERC];
// fp16 weights, transposed to [N][K]
__device__ __half g_wq[DEPTHL * DIMC * HIDD];
__device__ __half g_wkv[DEPTHL * DIMC * 2 * HIDD];
__device__ __half g_wo[DEPTHL * HIDD * DIMC];
__device__ __half g_wfi[DEPTHL * DIMC * INNERC];
__device__ __half g_wfo[DEPTHL * INNERC * DIMC];

// ---------------- helpers ----------------------------------------------------
#define MMA_F16(c, a0, a1, a2, a3, b0, b1)                                      \
    asm volatile(                                                               \
        "mma.sync.aligned.m16n8k16.row.col.f32.f16.f16.f32 "                    \
        "{%0,%1,%2,%3},{%4,%5,%6,%7},{%8,%9},{%0,%1,%2,%3};"                    \
        : "+f"(c[0]), "+f"(c[1]), "+f"(c[2]), "+f"(c[3])                        \
        : "r"(a0), "r"(a1), "r"(a2), "r"(a3), "r"(b0), "r"(b1))

#define CPA16(dst, src)                                                         \
    asm volatile("cp.async.cg.shared.global [%0], [%1], 16;" ::"r"(dst), "l"(src))
#define CP_COMMIT() asm volatile("cp.async.commit_group;")
#define CP_WAIT(n)  asm volatile("cp.async.wait_group %0;" ::"n"(n))

__device__ __forceinline__ uint32_t smem_u32(const void* p) {
    return (uint32_t)__cvta_generic_to_shared(p);
}
__device__ __forceinline__ uint32_t ld32h(const __half* p) {
    return *(const uint32_t*)p;
}
__device__ __forceinline__ uint32_t packh2(float lo, float hi) {
    __half2 h = __floats2half2_rn(lo, hi);
    return *(uint32_t*)&h;
}

// ---------------- weight round+transpose: [D][K][N] f32 -> [D][N][K] f16 -----
__global__ void transpose_h_k(const float* __restrict__ in, __half* __restrict__ out,
                              int K, int N) {
    __shared__ float tile[32][33];
    int d = blockIdx.z;
    int n0 = blockIdx.x * 32, k0 = blockIdx.y * 32;
    int tn = threadIdx.x & 31, tk = threadIdx.x >> 5;
    const float* inp = in + ((size_t)d * K + k0) * N + n0;
#pragma unroll
    for (int i = 0; i < 4; i++)
        tile[tk + 8 * i][tn] = inp[(size_t)(tk + 8 * i) * N + tn];
    __syncthreads();
    __half* op = out + ((size_t)d * N + n0) * K + k0;
#pragma unroll
    for (int i = 0; i < 4; i++)
        op[(size_t)(tk + 8 * i) * K + tn] = __float2half_rn(tile[tn][tk + 8 * i]);
}

__global__ void silu_time_k(const float* __restrict__ tm, float* __restrict__ out) {
    int i = blockIdx.x * 256 + threadIdx.x;
    if (i < BB * TCDD) {
        float v = tm[i];
        out[i] = v / (1.f + __expf(-v));
    }
}

__global__ void init_x_k(const float* __restrict__ xin, const float* __restrict__ mask,
                         float* __restrict__ x) {
    int i = blockIdx.x * 256 + threadIdx.x;
    if (i < BB * NN * DIMC) x[i] = xin[i] * mask[i / DIMC];
}

// all layers' time-conditioning GEMVs. 4 accumulators x unroll 4 -> 16 loads in flight.
__global__ __launch_bounds__(256)
void time_all_k(const float* __restrict__ tact,
                const float* __restrict__ atw, const float* __restrict__ atb,
                const float* __restrict__ ftw, const float* __restrict__ ftb,
                float* __restrict__ scsh_a, float* __restrict__ scsh_f) {
    __shared__ float red[4][64];
    int colL = threadIdx.x & 63, kg = threadIdx.x >> 6;
    int col = blockIdx.x * 64 + colL;
    int b = blockIdx.y, d = blockIdx.z;
    const float* t = tact + b * TCDD + kg * 128;
    const float* W;
    const float* bias;
    float* out;
    int Ncols, c;
    if (col < 2 * DIMC) {
        Ncols = 2 * DIMC;
        c = col;
        W = atw + (size_t)d * TCDD * Ncols;
        bias = atb + (size_t)d * Ncols;
        out = scsh_a + ((size_t)d * BB + b) * Ncols;
    } else {
        Ncols = 2 * INNERC;
        c = col - 2 * DIMC;
        W = ftw + (size_t)d * TCDD * Ncols;
        bias = ftb + (size_t)d * Ncols;
        out = scsh_f + ((size_t)d * BB + b) * Ncols;
    }
    const float* Wp = W + (size_t)(kg * 128) * Ncols + c;
    float a0 = 0.f, a1 = 0.f, a2 = 0.f, a3 = 0.f;
#pragma unroll 4
    for (int k = 0; k < 128; k += 4) {
        a0 += t[k] * Wp[(size_t)k * Ncols];
        a1 += t[k + 1] * Wp[(size_t)(k + 1) * Ncols];
        a2 += t[k + 2] * Wp[(size_t)(k + 2) * Ncols];
        a3 += t[k + 3] * Wp[(size_t)(k + 3) * Ncols];
    }
    red[kg][colL] = (a0 + a1) + (a2 + a3);
    __syncthreads();
    if (kg == 0)
        out[c] = red[0][colL] + red[1][colL] + red[2][colL] + red[3][colL] + bias[c];
}

// Warp-per-row LayerNorm (+AdaLN mod, +row mask); fp16 outputs.
__global__ __launch_bounds__(256)
void ln_mod_k(const float* __restrict__ x, const float* __restrict__ g,
              const float* __restrict__ scsh, const float* __restrict__ mask,
              __half* __restrict__ out, __half* __restrict__ out2, int useMod) {
    int warp = threadIdx.x >> 5, lane = threadIdx.x & 31;
    int row = blockIdx.x * 8 + warp;
    const float* xr = x + (size_t)row * DIMC;
    float4 v[4];
    float s = 0.f, sq = 0.f;
#pragma unroll
    for (int i = 0; i < 4; i++) {
        v[i] = *(const float4*)(xr + i * 128 + lane * 4);
        s += v[i].x + v[i].y + v[i].z + v[i].w;
        sq += v[i].x * v[i].x + v[i].y * v[i].y + v[i].z * v[i].z + v[i].w * v[i].w;
    }
#pragma unroll
    for (int off = 16; off > 0; off >>= 1) {
        s += __shfl_xor_sync(0xffffffffu, s, off);
        sq += __shfl_xor_sync(0xffffffffu, sq, off);
    }
    float m = s * (1.f / DIMC);
    float rstd = rsqrtf(sq * (1.f / DIMC) - m * m + LNEPS);
    int b = row / NN;
    float mk = mask ? mask[row] : 1.f;
#pragma unroll
    for (int i = 0; i < 4; i++) {
        int c = i * 128 + lane * 4;
        float4 gg = *(const float4*)(g + c);
        float4 o;
        o.x = (v[i].x - m) * rstd * gg.x;
        o.y = (v[i].y - m) * rstd * gg.y;
        o.z = (v[i].z - m) * rstd * gg.z;
        o.w = (v[i].w - m) * rstd * gg.w;
        if (useMod) {
            const float* scp = scsh + b * 2 * DIMC + c;
            const float* shp = scp + DIMC;
            float4 sc = *(const float4*)scp, sh = *(const float4*)shp;
            o.x = o.x * (sc.x + 1.f) + sh.x;
            o.y = o.y * (sc.y + 1.f) + sh.y;
            o.z = o.z * (sc.z + 1.f) + sh.z;
            o.w = o.w * (sc.w + 1.f) + sh.w;
        }
        uint2 pk;
        pk.x = packh2(o.x * mk, o.y * mk);
        pk.y = packh2(o.z * mk, o.w * mk);
        *(uint2*)(out + (size_t)row * DIMC + c) = pk;
        if (out2) {
            uint2 p2;
            p2.x = packh2(v[i].x, v[i].y);
            p2.y = packh2(v[i].z, v[i].w);
            *(uint2*)(out2 + (size_t)row * DIMC + c) = p2;
        }
    }
}

// ---------------- fp16 128x128 GEMM, k-tile 64, 2-stage -----------------------
// A [M][K] f16; Bt [N][K] f16. smem rows stride 72 halves (144B) conflict-free.
#define AH_TILE 9216                // 128*72 halves
#define HSTG_BYTES 36864            // (128+128)*72*2 bytes
#define HG_SMEM (2 * HSTG_BYTES)    // 73,728 B -> 2 CTAs/SM

__device__ __forceinline__ void hgemm_body(
    const __half* __restrict__ A, const __half* __restrict__ Bt,
    void* __restrict__ Cv, int Ncols, int K,
    const float* __restrict__ bias, const float* __restrict__ residual,
    const float* __restrict__ rowmask, const float* __restrict__ mod,
    float alpha, int mode, int rowBase, int colBase, char* smraw) {
    uint32_t smB = smem_u32(smraw);
    int t = threadIdx.x;
    int lane = t & 31, warp = t >> 5;
    int gid = lane >> 2, tig = lane & 3;
    int wr = warp >> 1, wc = warp & 1;

    const __half* gA = A + (size_t)rowBase * K;
    const __half* gB = Bt + (size_t)colBase * K;

    float acc[2][8][4];
#pragma unroll
    for (int i = 0; i < 2; i++)
#pragma unroll
        for (int j = 0; j < 8; j++)
#pragma unroll
            for (int c = 0; c < 4; c++) acc[i][j][c] = 0.f;

    int T = K >> 6;

#define H_ISSUE(kt, st)                                                         \
    {                                                                           \
        int kk0 = (kt) << 6;                                                    \
        uint32_t base = smB + (st) * HSTG_BYTES;                                \
        _Pragma("unroll") for (int l = 0; l < 4; l++) {                         \
            int idx = t + 256 * l;                                              \
            int rr = idx >> 3, c8 = idx & 7;                                    \
            CPA16(base + rr * 144 + c8 * 16,                                    \
                  gA + (size_t)rr * K + kk0 + c8 * 8);                          \
        }                                                                       \
        _Pragma("unroll") for (int l = 0; l < 4; l++) {                         \
            int idx = t + 256 * l;                                              \
            int rr = idx >> 3, c8 = idx & 7;                                    \
            CPA16(base + 18432 + rr * 144 + c8 * 16,                            \
                  gB + (size_t)rr * K + kk0 + c8 * 8);                          \
        }                                                                       \
        CP_COMMIT();                                                            \
    }

    H_ISSUE(0, 0);
    for (int it = 0; it < T; it++) {
        if (it + 1 < T) {
            H_ISSUE(it + 1, (it + 1) & 1);
            CP_WAIT(1);
        } else {
            CP_WAIT(0);
        }
        __syncthreads();
        const __half* Asb = (const __half*)(smraw + (it & 1) * HSTG_BYTES);
        const __half* Bsb = Asb + AH_TILE;
#pragma unroll
        for (int ks = 0; ks < 64; ks += 16) {
            uint32_t a[2][4];
#pragma unroll
            for (int mt = 0; mt < 2; mt++) {
                int m0 = wr * 32 + mt * 16;
                a[mt][0] = ld32h(&Asb[(m0 + gid) * 72 + ks + 2 * tig]);
                a[mt][1] = ld32h(&Asb[(m0 + gid + 8) * 72 + ks + 2 * tig]);
                a[mt][2] = ld32h(&Asb[(m0 + gid) * 72 + ks + 2 * tig + 8]);
                a[mt][3] = ld32h(&Asb[(m0 + gid + 8) * 72 + ks + 2 * tig + 8]);
            }
            uint32_t b[8][2];
#pragma unroll
            for (int nt = 0; nt < 8; nt++) {
                int n0 = wc * 64 + nt * 8;
                b[nt][0] = ld32h(&Bsb[(n0 + gid) * 72 + ks + 2 * tig]);
                b[nt][1] = ld32h(&Bsb[(n0 + gid) * 72 + ks + 2 * tig + 8]);
            }
#pragma unroll
            for (int mt = 0; mt < 2; mt++)
#pragma unroll
                for (int nt = 0; nt < 8; nt++)
                    MMA_F16(acc[mt][nt], a[mt][0], a[mt][1], a[mt][2], a[mt][3],
                            b[nt][0], b[nt][1]);
        }
        __syncthreads();
    }
#undef H_ISSUE

#pragma unroll
    for (int mt = 0; mt < 2; mt++)
#pragma unroll
        for (int half = 0; half < 2; half++) {
            int i = rowBase + wr * 32 + mt * 16 + gid + half * 8;
            int b = i / NN;
            float rm = (mode >= 2) ? rowmask[i] : 1.f;
#pragma unroll
            for (int nt = 0; nt < 8; nt++) {
                int j = colBase + wc * 64 + nt * 8 + tig * 2;
                size_t off = (size_t)i * Ncols + j;
                float v0 = acc[mt][nt][half * 2 + 0] * alpha;
                float v1 = acc[mt][nt][half * 2 + 1] * alpha;
                if (mode == 0) {
                    *(uint32_t*)((__half*)Cv + off) = packh2(v0, v1);
                } else if (mode == 1) {
                    v0 += bias[j];
                    v1 += bias[j + 1];
                    v0 = v0 / (1.f + __expf(-v0));
                    v1 = v1 / (1.f + __expf(-v1));
                    float sc0 = mod[b * 2 * Ncols + j], sc1 = mod[b * 2 * Ncols + j + 1];
                    float sh0 = mod[b * 2 * Ncols + Ncols + j];
                    float sh1 = mod[b * 2 * Ncols + Ncols + j + 1];
                    v0 = v0 * (sc0 + 1.f) + sh0;
                    v1 = v1 * (sc1 + 1.f) + sh1;
                    *(uint32_t*)((__half*)Cv + off) = packh2(v0, v1);
                } else if (mode == 2) {
                    float2 r = *(const float2*)(residual + off);
                    *(float2*)((float*)Cv + off) =
                        make_float2(r.x + v0 * rm, r.y + v1 * rm);
                } else {
                    float2 r = *(const float2*)(residual + off);
                    *(float2*)((float*)Cv + off) =
                        make_float2((r.x + v0 + bias[j]) * rm,
                                    (r.y + v1 + bias[j + 1]) * rm);
                }
            }
        }
}

__global__ __launch_bounds__(256, 2)
void hgemm_k(const __half* __restrict__ A, const __half* __restrict__ Bt,
             void* __restrict__ C, int Ncols, int K,
             const float* __restrict__ bias, const float* __restrict__ residual,
             const float* __restrict__ rowmask, const float* __restrict__ mod,
             float alpha, int mode) {
    extern __shared__ char smraw[];
    hgemm_body(A, Bt, C, Ncols, K, bias, residual, rowmask, mod, alpha, mode,
               blockIdx.y * 128, blockIdx.x * 128, smraw);
}

// merged q + kv: blockIdx.x < 4 -> q, else kv
__global__ __launch_bounds__(256, 2)
void qkv_k(const __half* __restrict__ xn, const __half* __restrict__ xh,
           const __half* __restrict__ wq, const __half* __restrict__ wkv,
           __half* __restrict__ q, __half* __restrict__ kv) {
    extern __shared__ char smraw[];
    if (blockIdx.x < HIDD / 128) {
        hgemm_body(xn, wq, q, HIDD, DIMC, nullptr, nullptr, nullptr, nullptr,
                   SCALEQ, 0, blockIdx.y * 128, blockIdx.x * 128, smraw);
    } else {
        hgemm_body(xh, wkv, kv, 2 * HIDD, DIMC, nullptr, nullptr, nullptr, nullptr,
                   1.f, 0, blockIdx.y * 128, (blockIdx.x - HIDD / 128) * 128, smraw);
    }
}

// ---------------- fp16 flash attention (R13, unchanged) -----------------------
#define QS_H (128 * 72)
#define KS_H (64 * 72)
#define VS_H (64 * 72)
#define FLASH_SMEM ((QS_H + KS_H + VS_H) * 2 + (65 + 64 + 64) * 4 + 16)

__global__ __launch_bounds__(256, 2)
void flash_k(const __half* __restrict__ q, const __half* __restrict__ kv,
             const int* __restrict__ ri, const float* __restrict__ mask,
             const float* __restrict__ rw, const float* __restrict__ rb,
             __half* __restrict__ ao) {
    extern __shared__ char smraw[];
    __half* Qs = (__half*)smraw;
    __half* Ks = Qs + QS_H;
    __half* Vs = Ks + KS_H;
    float* rws = (float*)(Vs + VS_H);
    float* mjs = rws + 65;
    int* rji = (int*)(mjs + 64);

    int b = blockIdx.y / HEADS, h = blockIdx.y % HEADS;
    int i0 = blockIdx.x * 128;
    int t = threadIdx.x;
    int lane = t & 31, warp = t >> 5;
    int gid = lane >> 2, tig = lane & 3;

#pragma unroll
    for (int l = 0; l < 8; l++) {
        int idx = t + 256 * l;
        int r = idx >> 4, dv = idx & 15;
        *(uint2*)&Qs[r * 72 + dv * 4] =
            *(const uint2*)(q + (size_t)(b * NN + i0 + r) * HIDD + h * DH + dv * 4);
    }
    if (t < 65) rws[t] = rw[t * HEADS + h] + rb[h];
    __syncthreads();

    int row0 = i0 + warp * 16 + gid;
    int row1 = row0 + 8;
    int ri0 = ri[b * NN + row0], ri1 = ri[b * NN + row1];
    float mi0 = mask[b * NN + row0], mi1 = mask[b * NN + row1];

    float O[8][4];
#pragma unroll
    for (int nt = 0; nt < 8; nt++)
#pragma unroll
        for (int c = 0; c < 4; c++) O[nt][c] = 0.f;
    float m0 = -1e30f, m1 = -1e30f, l0 = 0.f, l1 = 0.f;

    for (int j0 = 0; j0 < NN; j0 += 64) {
#pragma unroll
        for (int l = 0; l < 4; l++) {
            int idx = t + 256 * l;
            int r = idx >> 4, dv = idx & 15;
            *(uint2*)&Ks[r * 72 + dv * 4] =
                *(const uint2*)(kv + (size_t)(b * NN + j0 + r) * 2 * HIDD + h * DH +
                                dv * 4);
        }
        {
            int j = t & 63, dg = t >> 6;
            const __half* vsrc = kv + ((size_t)(b * NN + j0 + j) * 2 + 1) * HIDD +
                                 h * DH + dg * 16;
            __half tmp[16];
            *(uint4*)tmp = *(const uint4*)vsrc;
            *(uint4*)(tmp + 8) = *(const uint4*)(vsrc + 8);
#pragma unroll
            for (int i = 0; i < 16; i++) Vs[(dg * 16 + i) * 72 + j] = tmp[i];
        }
        if (t < 64) {
            rji[t] = ri[b * NN + j0 + t];
            mjs[t] = mask[b * NN + j0 + t];
        }
        __syncthreads();

        float S[8][4];
#pragma unroll
        for (int nt = 0; nt < 8; nt++)
#pragma unroll
            for (int c = 0; c < 4; c++) S[nt][c] = 0.f;
#pragma unroll
        for (int kt = 0; kt < 4; kt++) {
            int ks = kt * 16;
            uint32_t a0 = ld32h(&Qs[(warp * 16 + gid) * 72 + ks + 2 * tig]);
            uint32_t a1 = ld32h(&Qs[(warp * 16 + gid + 8) * 72 + ks + 2 * tig]);
            uint32_t a2 = ld32h(&Qs[(warp * 16 + gid) * 72 + ks + 2 * tig + 8]);
            uint32_t a3 = ld32h(&Qs[(warp * 16 + gid + 8) * 72 + ks + 2 * tig + 8]);
#pragma unroll
            for (int nt = 0; nt < 8; nt++) {
                uint32_t b0 = ld32h(&Ks[(nt * 8 + gid) * 72 + ks + 2 * tig]);
                uint32_t b1 = ld32h(&Ks[(nt * 8 + gid) * 72 + ks + 2 * tig + 8]);
                MMA_F16(S[nt], a0, a1, a2, a3, b0, b1);
            }
        }

#pragma unroll
        for (int nt = 0; nt < 8; nt++) {
            int jl0 = nt * 8 + 2 * tig, jl1 = jl0 + 1;
            int rj0 = rji[jl0], rj1 = rji[jl1];
            float mj0 = mjs[jl0], mj1 = mjs[jl1];
            int d00 = min(max(ri0 - rj0, -MAXREL), MAXREL) + MAXREL;
            int d01 = min(max(ri0 - rj1, -MAXREL), MAXREL) + MAXREL;
            int d10 = min(max(ri1 - rj0, -MAXREL), MAXREL) + MAXREL;
            int d11 = min(max(ri1 - rj1, -MAXREL), MAXREL) + MAXREL;
            S[nt][0] += rws[d00] - (1.f - mi0 * mj0) * 1e6f;
            S[nt][1] += rws[d01] - (1.f - mi0 * mj1) * 1e6f;
            S[nt][2] += rws[d10] - (1.f - mi1 * mj0) * 1e6f;
            S[nt][3] += rws[d11] - (1.f - mi1 * mj1) * 1e6f;
        }

        float mx0 = -1e30f, mx1 = -1e30f;
#pragma unroll
        for (int nt = 0; nt < 8; nt++) {
            mx0 = fmaxf(mx0, fmaxf(S[nt][0], S[nt][1]));
            mx1 = fmaxf(mx1, fmaxf(S[nt][2], S[nt][3]));
        }
        mx0 = fmaxf(mx0, __shfl_xor_sync(0xffffffffu, mx0, 1));
        mx0 = fmaxf(mx0, __shfl_xor_sync(0xffffffffu, mx0, 2));
        mx1 = fmaxf(mx1, __shfl_xor_sync(0xffffffffu, mx1, 1));
        mx1 = fmaxf(mx1, __shfl_xor_sync(0xffffffffu, mx1, 2));
        float m0n = fmaxf(m0, mx0), m1n = fmaxf(m1, mx1);
        float sc0 = __expf(m0 - m0n), sc1 = __expf(m1 - m1n);
        m0 = m0n; m1 = m1n;

        float sum0 = 0.f, sum1 = 0.f;
#pragma unroll
        for (int nt = 0; nt < 8; nt++) {
            S[nt][0] = __expf(S[nt][0] - m0n);
            S[nt][1] = __expf(S[nt][1] - m0n);
            S[nt][2] = __expf(S[nt][2] - m1n);
            S[nt][3] = __expf(S[nt][3] - m1n);
            sum0 += S[nt][0] + S[nt][1];
            sum1 += S[nt][2] + S[nt][3];
        }
        sum0 += __shfl_xor_sync(0xffffffffu, sum0, 1);
        sum0 += __shfl_xor_sync(0xffffffffu, sum0, 2);
        sum1 += __shfl_xor_sync(0xffffffffu, sum1, 1);
        sum1 += __shfl_xor_sync(0xffffffffu, sum1, 2);
        l0 = l0 * sc0 + sum0;
        l1 = l1 * sc1 + sum1;

#pragma unroll
        for (int nt = 0; nt < 8; nt++) {
            O[nt][0] *= sc0; O[nt][1] *= sc0;
            O[nt][2] *= sc1; O[nt][3] *= sc1;
        }

#pragma unroll
        for (int kt = 0; kt < 4; kt++) {
            uint32_t a0 = packh2(S[2 * kt][0], S[2 * kt][1]);
            uint32_t a1 = packh2(S[2 * kt][2], S[2 * kt][3]);
            uint32_t a2 = packh2(S[2 * kt + 1][0], S[2 * kt + 1][1]);
            uint32_t a3 = packh2(S[2 * kt + 1][2], S[2 * kt + 1][3]);
#pragma unroll
            for (int nt = 0; nt < 8; nt++) {
                uint32_t b0 = ld32h(&Vs[(nt * 8 + gid) * 72 + kt * 16 + 2 * tig]);
                uint32_t b1 = ld32h(&Vs[(nt * 8 + gid) * 72 + kt * 16 + 2 * tig + 8]);
                MMA_F16(O[nt], a0, a1, a2, a3, b0, b1);
            }
        }
        __syncthreads();
    }

    float inv0 = 1.f / l0, inv1 = 1.f / l1;
#pragma unroll
    for (int nt = 0; nt < 8; nt++) {
        int dd = nt * 8 + tig * 2;
        *(uint32_t*)(ao + (size_t)(b * NN + row0) * HIDD + h * DH + dd) =
            packh2(O[nt][0] * inv0, O[nt][1] * inv0);
        *(uint32_t*)(ao + (size_t)(b * NN + row1) * HIDD + h * DH + dd) =
            packh2(O[nt][2] * inv1, O[nt][3] * inv1);
    }
}

// ---------------- launch -----------------------------------------------------
extern "C" void kernel_launch(void* const* d_in, const int* in_sizes, int n_in,
                              void* d_out, int out_size) {
    const float* x_in      = (const float*)d_in[0];
    const float* time_in   = (const float*)d_in[1];
    const float* seq_mask  = (const float*)d_in[2];
    const int*   res_idx   = (const int*)d_in[3];
    const float* relpos_w  = (const float*)d_in[4];
    const float* relpos_b  = (const float*)d_in[5];
    const float* attn_g    = (const float*)d_in[6];
    const float* attn_tw   = (const float*)d_in[7];
    const float* attn_tb   = (const float*)d_in[8];
    const float* to_q_w    = (const float*)d_in[9];
    const float* to_kv_w   = (const float*)d_in[10];
    const float* to_out_w  = (const float*)d_in[11];
    const float* ff_g      = (const float*)d_in[12];
    const float* ff_tw     = (const float*)d_in[13];
    const float* ff_tb     = (const float*)d_in[14];
    const float* ff_in_w   = (const float*)d_in[15];
    const float* ff_in_b   = (const float*)d_in[16];
    const float* ff_out_w  = (const float*)d_in[17];
    const float* ff_out_b  = (const float*)d_in[18];

    float *tact, *scsh_a, *scsh_f;
    __half *xn, *xh, *q, *kv, *ao, *hb, *wq, *wkv, *wo, *wfi, *wfo;
    cudaGetSymbolAddress((void**)&tact, g_tact);
    cudaGetSymbolAddress((void**)&scsh_a, g_scsh_a);
    cudaGetSymbolAddress((void**)&scsh_f, g_scsh_f);
    cudaGetSymbolAddress((void**)&xn, g_xn);
    cudaGetSymbolAddress((void**)&xh, g_xh);
    cudaGetSymbolAddress((void**)&q, g_q);
    cudaGetSymbolAddress((void**)&kv, g_kv);
    cudaGetSymbolAddress((void**)&ao, g_ao);
    cudaGetSymbolAddress((void**)&hb, g_hb);
    cudaGetSymbolAddress((void**)&wq, g_wq);
    cudaGetSymbolAddress((void**)&wkv, g_wkv);
    cudaGetSymbolAddress((void**)&wo, g_wo);
    cudaGetSymbolAddress((void**)&wfi, g_wfi);
    cudaGetSymbolAddress((void**)&wfo, g_wfo);

    cudaFuncSetAttribute(hgemm_k, cudaFuncAttributeMaxDynamicSharedMemorySize,
                         HG_SMEM);
    cudaFuncSetAttribute(qkv_k, cudaFuncAttributeMaxDynamicSharedMemorySize,
                         HG_SMEM);
    cudaFuncSetAttribute(flash_k, cudaFuncAttributeMaxDynamicSharedMemorySize,
                         FLASH_SMEM);

    float* x = (float*)d_out;
    const int M = BB * NN;

    transpose_h_k<<<dim3(HIDD / 32, DIMC / 32, DEPTHL), 256>>>(to_q_w, wq, DIMC, HIDD);
    transpose_h_k<<<dim3(2 * HIDD / 32, DIMC / 32, DEPTHL), 256>>>(to_kv_w, wkv, DIMC,
                                                                   2 * HIDD);
    transpose_h_k<<<dim3(DIMC / 32, HIDD / 32, DEPTHL), 256>>>(to_out_w, wo, HIDD, DIMC);
    transpose_h_k<<<dim3(INNERC / 32, DIMC / 32, DEPTHL), 256>>>(ff_in_w, wfi, DIMC,
                                                                 INNERC);
    transpose_h_k<<<dim3(DIMC / 32, INNERC / 32, DEPTHL), 256>>>(ff_out_w, wfo, INNERC,
                                                                 DIMC);

    init_x_k<<<(BB * NN * DIMC + 255) / 256, 256>>>(x_in, seq_mask, x);
    silu_time_k<<<(BB * TCDD + 255) / 256, 256>>>(time_in, tact);
    time_all_k<<<dim3((2 * DIMC + 2 * INNERC) / 64, BB, DEPTHL), 256>>>(
        tact, attn_tw, attn_tb, ff_tw, ff_tb, scsh_a, scsh_f);

    for (int d = 0; d < DEPTHL; d++) {
        // --- attention block ---
        ln_mod_k<<<M / 8, 256>>>(x, attn_g + d * DIMC,
                                 scsh_a + (size_t)d * BB * 2 * DIMC, seq_mask,
                                 xn, xh, 1);
        qkv_k<<<dim3(12, M / 128), 256, HG_SMEM>>>(
            xn, xh, wq + (size_t)d * DIMC * HIDD, wkv + (size_t)d * DIMC * 2 * HIDD,
            q, kv);
        flash_k<<<dim3(NN / 128, BB * HEADS), 256, FLASH_SMEM>>>(
            q, kv, res_idx, seq_mask, relpos_w, relpos_b, ao);
        hgemm_k<<<dim3(DIMC / 128, M / 128), 256, HG_SMEM>>>(
            ao, wo + (size_t)d * HIDD * DIMC, x, DIMC, HIDD,
            nullptr, x, seq_mask, nullptr, 1.f, 2);

        // --- feed-forward block ---
        ln_mod_k<<<M / 8, 256>>>(x, ff_g + d * DIMC, nullptr, nullptr, xn, nullptr, 0);
        hgemm_k<<<dim3(INNERC / 128, M / 128), 256, HG_SMEM>>>(
            xn, wfi + (size_t)d * DIMC * INNERC, hb, INNERC, DIMC,
            ff_in_b + (size_t)d * INNERC, nullptr, nullptr,
            scsh_f + (size_t)d * BB * 2 * INNERC, 1.f, 1);
        hgemm_k<<<dim3(DIMC / 128, M / 128), 256, HG_SMEM>>>(
            hb, wfo + (size_t)d * INNERC * DIMC, x, DIMC, INNERC,
            ff_out_b + (size_t)d * DIMC, x, seq_mask, nullptr, 1.f, 3);
    }
}

// round 15
// speedup vs baseline: 1.5910x; 1.0000x over previous
#include <cuda_runtime.h>
#include <cuda_fp16.h>
#include <math.h>
#include <stdint.h>

#define BB     4
#define NN     1024
#define DIMC   512
#define DEPTHL 4
#define HEADS  8
#define DH     64
#define TCDD   512
#define HIDD   512
#define INNERC 2048
#define MAXREL 32
#define SCALEQ 0.125f
#define LNEPS  1e-5f

// ---------------- scratch ----------------------------------------------------
__device__ float  g_tact[BB * TCDD];
__device__ float  g_scsh_a[DEPTHL * BB * 2 * DIMC];
__device__ float  g_scsh_f[DEPTHL * BB * 2 * INNERC];
__device__ __half g_xn[BB * NN * DIMC];
__device__ __half g_xh[BB * NN * DIMC];
__device__ __half g_q[BB * NN * HIDD];
__device__ __half g_kv[BB * NN * 2 * HIDD];
__device__ __half g_ao[BB * NN * HIDD];
__device__ __half g_hb[BB * NN * INNERC];
__device__ __half g_wq[DEPTHL * DIMC * HIDD];
__device__ __half g_wkv[DEPTHL * DIMC * 2 * HIDD];
__device__ __half g_wo[DEPTHL * HIDD * DIMC];
__device__ __half g_wfi[DEPTHL * DIMC * INNERC];
__device__ __half g_wfo[DEPTHL * INNERC * DIMC];

// ---------------- helpers ----------------------------------------------------
#define MMA_F16(c, a0, a1, a2, a3, b0, b1)                                      \
    asm volatile(                                                               \
        "mma.sync.aligned.m16n8k16.row.col.f32.f16.f16.f32 "                    \
        "{%0,%1,%2,%3},{%4,%5,%6,%7},{%8,%9},{%0,%1,%2,%3};"                    \
        : "+f"(c[0]), "+f"(c[1]), "+f"(c[2]), "+f"(c[3])                        \
        : "r"(a0), "r"(a1), "r"(a2), "r"(a3), "r"(b0), "r"(b1))

#define CPA16(dst, src)                                                         \
    asm volatile("cp.async.cg.shared.global [%0], [%1], 16;" ::"r"(dst), "l"(src))
#define CP_COMMIT() asm volatile("cp.async.commit_group;")
#define CP_WAIT(n)  asm volatile("cp.async.wait_group %0;" ::"n"(n))

__device__ __forceinline__ uint32_t smem_u32(const void* p) {
    return (uint32_t)__cvta_generic_to_shared(p);
}
__device__ __forceinline__ uint32_t ld32h(const __half* p) {
    return *(const uint32_t*)p;
}
__device__ __forceinline__ uint32_t packh2(float lo, float hi) {
    __half2 h = __floats2half2_rn(lo, hi);
    return *(uint32_t*)&h;
}

// ---------------- merged weight prep: 5 tensors, one launch -------------------
// each 32x32 tile: [D][K][N] f32 -> [D][N][K] f16.  3072 tiles per depth.
__global__ void prep_w_k(const float* sq, __half* dq, const float* skv, __half* dkv,
                         const float* so, __half* dof, const float* sfi, __half* dfi,
                         const float* sfo, __half* dfo) {
    __shared__ float tile[32][33];
    int bid = blockIdx.x;
    int d = bid / 3072, r = bid % 3072;
    const float* src;
    __half* dst;
    int K, N, r2;
    if (r < 256)       { src = sq;  dst = dq;  K = DIMC;   N = HIDD;     r2 = r; }
    else if (r < 768)  { src = skv; dst = dkv; K = DIMC;   N = 2 * HIDD; r2 = r - 256; }
    else if (r < 1024) { src = so;  dst = dof; K = HIDD;   N = DIMC;     r2 = r - 768; }
    else if (r < 2048) { src = sfi; dst = dfi; K = DIMC;   N = INNERC;   r2 = r - 1024; }
    else               { src = sfo; dst = dfo; K = INNERC; N = DIMC;     r2 = r - 2048; }
    int ntiles = N >> 5;
    int nt = r2 % ntiles, kt = r2 / ntiles;
    int n0 = nt * 32, k0 = kt * 32;
    int tn = threadIdx.x & 31, tk = threadIdx.x >> 5;
    const float* inp = src + ((size_t)d * K + k0) * N + n0;
#pragma unroll
    for (int i = 0; i < 4; i++)
        tile[tk + 8 * i][tn] = inp[(size_t)(tk + 8 * i) * N + tn];
    __syncthreads();
    __half* op = dst + ((size_t)d * N + n0) * K + k0;
#pragma unroll
    for (int i = 0; i < 4; i++)
        op[(size_t)(tk + 8 * i) * K + tn] = __float2half_rn(tile[tn][tk + 8 * i]);
}

// init_x (blocks 0..8191) + silu_time (block 8192)
__global__ void prep_x_k(const float* __restrict__ xin, const float* __restrict__ mask,
                         float* __restrict__ x, const float* __restrict__ tm,
                         float* __restrict__ tact) {
    if (blockIdx.x < 8192) {
        int i = blockIdx.x * 256 + threadIdx.x;
        x[i] = xin[i] * mask[i / DIMC];
    } else {
#pragma unroll
        for (int u = 0; u < 8; u++) {
            int i = threadIdx.x + 256 * u;
            float v = tm[i];
            tact[i] = v / (1.f + __expf(-v));
        }
    }
}

// all layers' time-conditioning GEMVs. 4 acc x unroll 4.
__global__ __launch_bounds__(256)
void time_all_k(const float* __restrict__ tact,
                const float* __restrict__ atw, const float* __restrict__ atb,
                const float* __restrict__ ftw, const float* __restrict__ ftb,
                float* __restrict__ scsh_a, float* __restrict__ scsh_f) {
    __shared__ float red[4][64];
    int colL = threadIdx.x & 63, kg = threadIdx.x >> 6;
    int col = blockIdx.x * 64 + colL;
    int b = blockIdx.y, d = blockIdx.z;
    const float* t = tact + b * TCDD + kg * 128;
    const float* W;
    const float* bias;
    float* out;
    int Ncols, c;
    if (col < 2 * DIMC) {
        Ncols = 2 * DIMC;
        c = col;
        W = atw + (size_t)d * TCDD * Ncols;
        bias = atb + (size_t)d * Ncols;
        out = scsh_a + ((size_t)d * BB + b) * Ncols;
    } else {
        Ncols = 2 * INNERC;
        c = col - 2 * DIMC;
        W = ftw + (size_t)d * TCDD * Ncols;
        bias = ftb + (size_t)d * Ncols;
        out = scsh_f + ((size_t)d * BB + b) * Ncols;
    }
    const float* Wp = W + (size_t)(kg * 128) * Ncols + c;
    float a0 = 0.f, a1 = 0.f, a2 = 0.f, a3 = 0.f;
#pragma unroll 4
    for (int k = 0; k < 128; k += 4) {
        a0 += t[k] * Wp[(size_t)k * Ncols];
        a1 += t[k + 1] * Wp[(size_t)(k + 1) * Ncols];
        a2 += t[k + 2] * Wp[(size_t)(k + 2) * Ncols];
        a3 += t[k + 3] * Wp[(size_t)(k + 3) * Ncols];
    }
    red[kg][colL] = (a0 + a1) + (a2 + a3);
    __syncthreads();
    if (kg == 0)
        out[c] = red[0][colL] + red[1][colL] + red[2][colL] + red[3][colL] + bias[c];
}

// Warp-per-row LayerNorm (+AdaLN mod, +row mask); fp16 outputs.
__global__ __launch_bounds__(256)
void ln_mod_k(const float* __restrict__ x, const float* __restrict__ g,
              const float* __restrict__ scsh, const float* __restrict__ mask,
              __half* __restrict__ out, __half* __restrict__ out2, int useMod) {
    int warp = threadIdx.x >> 5, lane = threadIdx.x & 31;
    int row = blockIdx.x * 8 + warp;
    const float* xr = x + (size_t)row * DIMC;
    float4 v[4];
    float s = 0.f, sq = 0.f;
#pragma unroll
    for (int i = 0; i < 4; i++) {
        v[i] = *(const float4*)(xr + i * 128 + lane * 4);
        s += v[i].x + v[i].y + v[i].z + v[i].w;
        sq += v[i].x * v[i].x + v[i].y * v[i].y + v[i].z * v[i].z + v[i].w * v[i].w;
    }
#pragma unroll
    for (int off = 16; off > 0; off >>= 1) {
        s += __shfl_xor_sync(0xffffffffu, s, off);
        sq += __shfl_xor_sync(0xffffffffu, sq, off);
    }
    float m = s * (1.f / DIMC);
    float rstd = rsqrtf(sq * (1.f / DIMC) - m * m + LNEPS);
    int b = row / NN;
    float mk = mask ? mask[row] : 1.f;
#pragma unroll
    for (int i = 0; i < 4; i++) {
        int c = i * 128 + lane * 4;
        float4 gg = *(const float4*)(g + c);
        float4 o;
        o.x = (v[i].x - m) * rstd * gg.x;
        o.y = (v[i].y - m) * rstd * gg.y;
        o.z = (v[i].z - m) * rstd * gg.z;
        o.w = (v[i].w - m) * rstd * gg.w;
        if (useMod) {
            const float* scp = scsh + b * 2 * DIMC + c;
            const float* shp = scp + DIMC;
            float4 sc = *(const float4*)scp, sh = *(const float4*)shp;
            o.x = o.x * (sc.x + 1.f) + sh.x;
            o.y = o.y * (sc.y + 1.f) + sh.y;
            o.z = o.z * (sc.z + 1.f) + sh.z;
            o.w = o.w * (sc.w + 1.f) + sh.w;
        }
        uint2 pk;
        pk.x = packh2(o.x * mk, o.y * mk);
        pk.y = packh2(o.z * mk, o.w * mk);
        *(uint2*)(out + (size_t)row * DIMC + c) = pk;
        if (out2) {
            uint2 p2;
            p2.x = packh2(v[i].x, v[i].y);
            p2.y = packh2(v[i].z, v[i].w);
            *(uint2*)(out2 + (size_t)row * DIMC + c) = p2;
        }
    }
}

// ---------------- fp16 128x128 GEMM, k-tile 64, 2-stage (R14) -----------------
#define AH_TILE 9216
#define HSTG_BYTES 36864
#define HG_SMEM (2 * HSTG_BYTES)

__device__ __forceinline__ void hgemm_body(
    const __half* __restrict__ A, const __half* __restrict__ Bt,
    void* __restrict__ Cv, int Ncols, int K,
    const float* __restrict__ bias, const float* __restrict__ residual,
    const float* __restrict__ rowmask, const float* __restrict__ mod,
    float alpha, int mode, int rowBase, int colBase, char* smraw) {
    uint32_t smB = smem_u32(smraw);
    int t = threadIdx.x;
    int lane = t & 31, warp = t >> 5;
    int gid = lane >> 2, tig = lane & 3;
    int wr = warp >> 1, wc = warp & 1;

    const __half* gA = A + (size_t)rowBase * K;
    const __half* gB = Bt + (size_t)colBase * K;

    float acc[2][8][4];
#pragma unroll
    for (int i = 0; i < 2; i++)
#pragma unroll
        for (int j = 0; j < 8; j++)
#pragma unroll
            for (int c = 0; c < 4; c++) acc[i][j][c] = 0.f;

    int T = K >> 6;

#define H_ISSUE(kt, st)                                                         \
    {                                                                           \
        int kk0 = (kt) << 6;                                                    \
        uint32_t base = smB + (st) * HSTG_BYTES;                                \
        _Pragma("unroll") for (int l = 0; l < 4; l++) {                         \
            int idx = t + 256 * l;                                              \
            int rr = idx >> 3, c8 = idx & 7;                                    \
            CPA16(base + rr * 144 + c8 * 16,                                    \
                  gA + (size_t)rr * K + kk0 + c8 * 8);                          \
        }                                                                       \
        _Pragma("unroll") for (int l = 0; l < 4; l++) {                         \
            int idx = t + 256 * l;                                              \
            int rr = idx >> 3, c8 = idx & 7;                                    \
            CPA16(base + 18432 + rr * 144 + c8 * 16,                            \
                  gB + (size_t)rr * K + kk0 + c8 * 8);                          \
        }                                                                       \
        CP_COMMIT();                                                            \
    }

    H_ISSUE(0, 0);
    for (int it = 0; it < T; it++) {
        if (it + 1 < T) {
            H_ISSUE(it + 1, (it + 1) & 1);
            CP_WAIT(1);
        } else {
            CP_WAIT(0);
        }
        __syncthreads();
        const __half* Asb = (const __half*)(smraw + (it & 1) * HSTG_BYTES);
        const __half* Bsb = Asb + AH_TILE;
#pragma unroll
        for (int ks = 0; ks < 64; ks += 16) {
            uint32_t a[2][4];
#pragma unroll
            for (int mt = 0; mt < 2; mt++) {
                int m0 = wr * 32 + mt * 16;
                a[mt][0] = ld32h(&Asb[(m0 + gid) * 72 + ks + 2 * tig]);
                a[mt][1] = ld32h(&Asb[(m0 + gid + 8) * 72 + ks + 2 * tig]);
                a[mt][2] = ld32h(&Asb[(m0 + gid) * 72 + ks + 2 * tig + 8]);
                a[mt][3] = ld32h(&Asb[(m0 + gid + 8) * 72 + ks + 2 * tig + 8]);
            }
            uint32_t b[8][2];
#pragma unroll
            for (int nt = 0; nt < 8; nt++) {
                int n0 = wc * 64 + nt * 8;
                b[nt][0] = ld32h(&Bsb[(n0 + gid) * 72 + ks + 2 * tig]);
                b[nt][1] = ld32h(&Bsb[(n0 + gid) * 72 + ks + 2 * tig + 8]);
            }
#pragma unroll
            for (int mt = 0; mt < 2; mt++)
#pragma unroll
                for (int nt = 0; nt < 8; nt++)
                    MMA_F16(acc[mt][nt], a[mt][0], a[mt][1], a[mt][2], a[mt][3],
                            b[nt][0], b[nt][1]);
        }
        __syncthreads();
    }
#undef H_ISSUE

#pragma unroll
    for (int mt = 0; mt < 2; mt++)
#pragma unroll
        for (int half = 0; half < 2; half++) {
            int i = rowBase + wr * 32 + mt * 16 + gid + half * 8;
            int b = i / NN;
            float rm = (mode >= 2) ? rowmask[i] : 1.f;
#pragma unroll
            for (int nt = 0; nt < 8; nt++) {
                int j = colBase + wc * 64 + nt * 8 + tig * 2;
                size_t off = (size_t)i * Ncols + j;
                float v0 = acc[mt][nt][half * 2 + 0] * alpha;
                float v1 = acc[mt][nt][half * 2 + 1] * alpha;
                if (mode == 0) {
                    *(uint32_t*)((__half*)Cv + off) = packh2(v0, v1);
                } else if (mode == 1) {
                    v0 += bias[j];
                    v1 += bias[j + 1];
                    v0 = v0 / (1.f + __expf(-v0));
                    v1 = v1 / (1.f + __expf(-v1));
                    float sc0 = mod[b * 2 * Ncols + j], sc1 = mod[b * 2 * Ncols + j + 1];
                    float sh0 = mod[b * 2 * Ncols + Ncols + j];
                    float sh1 = mod[b * 2 * Ncols + Ncols + j + 1];
                    v0 = v0 * (sc0 + 1.f) + sh0;
                    v1 = v1 * (sc1 + 1.f) + sh1;
                    *(uint32_t*)((__half*)Cv + off) = packh2(v0, v1);
                } else if (mode == 2) {
                    float2 r = *(const float2*)(residual + off);
                    *(float2*)((float*)Cv + off) =
                        make_float2(r.x + v0 * rm, r.y + v1 * rm);
                } else {
                    float2 r = *(const float2*)(residual + off);
                    *(float2*)((float*)Cv + off) =
                        make_float2((r.x + v0 + bias[j]) * rm,
                                    (r.y + v1 + bias[j + 1]) * rm);
                }
            }
        }
}

__global__ __launch_bounds__(256, 2)
void hgemm_k(const __half* __restrict__ A, const __half* __restrict__ Bt,
             void* __restrict__ C, int Ncols, int K,
             const float* __restrict__ bias, const float* __restrict__ residual,
             const float* __restrict__ rowmask, const float* __restrict__ mod,
             float alpha, int mode) {
    extern __shared__ char smraw[];
    hgemm_body(A, Bt, C, Ncols, K, bias, residual, rowmask, mod, alpha, mode,
               blockIdx.y * 128, blockIdx.x * 128, smraw);
}

__global__ __launch_bounds__(256, 2)
void qkv_k(const __half* __restrict__ xn, const __half* __restrict__ xh,
           const __half* __restrict__ wq, const __half* __restrict__ wkv,
           __half* __restrict__ q, __half* __restrict__ kv) {
    extern __shared__ char smraw[];
    if (blockIdx.x < HIDD / 128) {
        hgemm_body(xn, wq, q, HIDD, DIMC, nullptr, nullptr, nullptr, nullptr,
                   SCALEQ, 0, blockIdx.y * 128, blockIdx.x * 128, smraw);
    } else {
        hgemm_body(xh, wkv, kv, 2 * HIDD, DIMC, nullptr, nullptr, nullptr, nullptr,
                   1.f, 0, blockIdx.y * 128, (blockIdx.x - HIDD / 128) * 128, smraw);
    }
}

// ---------------- fp16 flash attention: outer j-tile 128, two 64-col passes ---
#define QS_H (128 * 72)
#define KS_H (128 * 72)
#define VS_H (64 * 136)
#define FLASH_SMEM ((QS_H + KS_H + VS_H) * 2 + (65 + 128 + 128) * 4 + 16)

__global__ __launch_bounds__(256, 2)
void flash_k(const __half* __restrict__ q, const __half* __restrict__ kv,
             const int* __restrict__ ri, const float* __restrict__ mask,
             const float* __restrict__ rw, const float* __restrict__ rb,
             __half* __restrict__ ao) {
    extern __shared__ char smraw[];
    __half* Qs = (__half*)smraw;
    __half* Ks = Qs + QS_H;
    __half* Vs = Ks + KS_H;      // [d][j], stride 136
    float* rws = (float*)(Vs + VS_H);
    float* mjs = rws + 65;
    int* rji = (int*)(mjs + 128);

    int b = blockIdx.y / HEADS, h = blockIdx.y % HEADS;
    int i0 = blockIdx.x * 128;
    int t = threadIdx.x;
    int lane = t & 31, warp = t >> 5;
    int gid = lane >> 2, tig = lane & 3;

#pragma unroll
    for (int l = 0; l < 8; l++) {
        int idx = t + 256 * l;
        int r = idx >> 4, dv = idx & 15;
        *(uint2*)&Qs[r * 72 + dv * 4] =
            *(const uint2*)(q + (size_t)(b * NN + i0 + r) * HIDD + h * DH + dv * 4);
    }
    if (t < 65) rws[t] = rw[t * HEADS + h] + rb[h];
    __syncthreads();

    int row0 = i0 + warp * 16 + gid;
    int row1 = row0 + 8;
    int ri0 = ri[b * NN + row0], ri1 = ri[b * NN + row1];
    float mi0 = mask[b * NN + row0], mi1 = mask[b * NN + row1];

    float O[8][4];
#pragma unroll
    for (int nt = 0; nt < 8; nt++)
#pragma unroll
        for (int c = 0; c < 4; c++) O[nt][c] = 0.f;
    float m0 = -1e30f, m1 = -1e30f, l0 = 0.f, l1 = 0.f;

    for (int j0 = 0; j0 < NN; j0 += 128) {
        // K fill: 128 rows x 64 halves
#pragma unroll
        for (int l = 0; l < 8; l++) {
            int idx = t + 256 * l;
            int r = idx >> 4, dv = idx & 15;
            *(uint2*)&Ks[r * 72 + dv * 4] =
                *(const uint2*)(kv + (size_t)(b * NN + j0 + r) * 2 * HIDD + h * DH +
                                dv * 4);
        }
        // V fill transposed [d][j]: two passes of 64 j's
#pragma unroll
        for (int p = 0; p < 2; p++) {
            int j = (t & 63) + 64 * p, dg = t >> 6;
            const __half* vsrc = kv + ((size_t)(b * NN + j0 + j) * 2 + 1) * HIDD +
                                 h * DH + dg * 16;
            __half tmp[16];
            *(uint4*)tmp = *(const uint4*)vsrc;
            *(uint4*)(tmp + 8) = *(const uint4*)(vsrc + 8);
#pragma unroll
            for (int i = 0; i < 16; i++) Vs[(dg * 16 + i) * 136 + j] = tmp[i];
        }
        if (t < 128) {
            rji[t] = ri[b * NN + j0 + t];
            mjs[t] = mask[b * NN + j0 + t];
        }
        __syncthreads();

#pragma unroll
        for (int jh = 0; jh < 2; jh++) {
            int jb = jh * 64;
            float S[8][4];
#pragma unroll
            for (int nt = 0; nt < 8; nt++)
#pragma unroll
                for (int c = 0; c < 4; c++) S[nt][c] = 0.f;
#pragma unroll
            for (int kt = 0; kt < 4; kt++) {
                int ks = kt * 16;
                uint32_t a0 = ld32h(&Qs[(warp * 16 + gid) * 72 + ks + 2 * tig]);
                uint32_t a1 = ld32h(&Qs[(warp * 16 + gid + 8) * 72 + ks + 2 * tig]);
                uint32_t a2 = ld32h(&Qs[(warp * 16 + gid) * 72 + ks + 2 * tig + 8]);
                uint32_t a3 = ld32h(&Qs[(warp * 16 + gid + 8) * 72 + ks + 2 * tig + 8]);
#pragma unroll
                for (int nt = 0; nt < 8; nt++) {
                    uint32_t b0 = ld32h(&Ks[(jb + nt * 8 + gid) * 72 + ks + 2 * tig]);
                    uint32_t b1 =
                        ld32h(&Ks[(jb + nt * 8 + gid) * 72 + ks + 2 * tig + 8]);
                    MMA_F16(S[nt], a0, a1, a2, a3, b0, b1);
                }
            }

#pragma unroll
            for (int nt = 0; nt < 8; nt++) {
                int jl0 = jb + nt * 8 + 2 * tig, jl1 = jl0 + 1;
                int rj0 = rji[jl0], rj1 = rji[jl1];
                float mj0 = mjs[jl0], mj1 = mjs[jl1];
                int d00 = min(max(ri0 - rj0, -MAXREL), MAXREL) + MAXREL;
                int d01 = min(max(ri0 - rj1, -MAXREL), MAXREL) + MAXREL;
                int d10 = min(max(ri1 - rj0, -MAXREL), MAXREL) + MAXREL;
                int d11 = min(max(ri1 - rj1, -MAXREL), MAXREL) + MAXREL;
                S[nt][0] += rws[d00] - (1.f - mi0 * mj0) * 1e6f;
                S[nt][1] += rws[d01] - (1.f - mi0 * mj1) * 1e6f;
                S[nt][2] += rws[d10] - (1.f - mi1 * mj0) * 1e6f;
                S[nt][3] += rws[d11] - (1.f - mi1 * mj1) * 1e6f;
            }

            float mx0 = -1e30f, mx1 = -1e30f;
#pragma unroll
            for (int nt = 0; nt < 8; nt++) {
                mx0 = fmaxf(mx0, fmaxf(S[nt][0], S[nt][1]));
                mx1 = fmaxf(mx1, fmaxf(S[nt][2], S[nt][3]));
            }
            mx0 = fmaxf(mx0, __shfl_xor_sync(0xffffffffu, mx0, 1));
            mx0 = fmaxf(mx0, __shfl_xor_sync(0xffffffffu, mx0, 2));
            mx1 = fmaxf(mx1, __shfl_xor_sync(0xffffffffu, mx1, 1));
            mx1 = fmaxf(mx1, __shfl_xor_sync(0xffffffffu, mx1, 2));
            float m0n = fmaxf(m0, mx0), m1n = fmaxf(m1, mx1);
            float sc0 = __expf(m0 - m0n), sc1 = __expf(m1 - m1n);
            m0 = m0n; m1 = m1n;

            float sum0 = 0.f, sum1 = 0.f;
#pragma unroll
            for (int nt = 0; nt < 8; nt++) {
                S[nt][0] = __expf(S[nt][0] - m0n);
                S[nt][1] = __expf(S[nt][1] - m0n);
                S[nt][2] = __expf(S[nt][2] - m1n);
                S[nt][3] = __expf(S[nt][3] - m1n);
                sum0 += S[nt][0] + S[nt][1];
                sum1 += S[nt][2] + S[nt][3];
            }
            sum0 += __shfl_xor_sync(0xffffffffu, sum0, 1);
            sum0 += __shfl_xor_sync(0xffffffffu, sum0, 2);
            sum1 += __shfl_xor_sync(0xffffffffu, sum1, 1);
            sum1 += __shfl_xor_sync(0xffffffffu, sum1, 2);
            l0 = l0 * sc0 + sum0;
            l1 = l1 * sc1 + sum1;

#pragma unroll
            for (int nt = 0; nt < 8; nt++) {
                O[nt][0] *= sc0; O[nt][1] *= sc0;
                O[nt][2] *= sc1; O[nt][3] *= sc1;
            }

#pragma unroll
            for (int kt = 0; kt < 4; kt++) {
                uint32_t a0 = packh2(S[2 * kt][0], S[2 * kt][1]);
                uint32_t a1 = packh2(S[2 * kt][2], S[2 * kt][3]);
                uint32_t a2 = packh2(S[2 * kt + 1][0], S[2 * kt + 1][1]);
                uint32_t a3 = packh2(S[2 * kt + 1][2], S[2 * kt + 1][3]);
#pragma unroll
                for (int nt = 0; nt < 8; nt++) {
                    uint32_t b0 =
                        ld32h(&Vs[(nt * 8 + gid) * 136 + jb + kt * 16 + 2 * tig]);
                    uint32_t b1 =
                        ld32h(&Vs[(nt * 8 + gid) * 136 + jb + kt * 16 + 2 * tig + 8]);
                    MMA_F16(O[nt], a0, a1, a2, a3, b0, b1);
                }
            }
        }
        __syncthreads();
    }

    float inv0 = 1.f / l0, inv1 = 1.f / l1;
#pragma unroll
    for (int nt = 0; nt < 8; nt++) {
        int dd = nt * 8 + tig * 2;
        *(uint32_t*)(ao + (size_t)(b * NN + row0) * HIDD + h * DH + dd) =
            packh2(O[nt][0] * inv0, O[nt][1] * inv0);
        *(uint32_t*)(ao + (size_t)(b * NN + row1) * HIDD + h * DH + dd) =
            packh2(O[nt][2] * inv1, O[nt][3] * inv1);
    }
}

// ---------------- launch -----------------------------------------------------
extern "C" void kernel_launch(void* const* d_in, const int* in_sizes, int n_in,
                              void* d_out, int out_size) {
    const float* x_in      = (const float*)d_in[0];
    const float* time_in   = (const float*)d_in[1];
    const float* seq_mask  = (const float*)d_in[2];
    const int*   res_idx   = (const int*)d_in[3];
    const float* relpos_w  = (const float*)d_in[4];
    const float* relpos_b  = (const float*)d_in[5];
    const float* attn_g    = (const float*)d_in[6];
    const float* attn_tw   = (const float*)d_in[7];
    const float* attn_tb   = (const float*)d_in[8];
    const float* to_q_w    = (const float*)d_in[9];
    const float* to_kv_w   = (const float*)d_in[10];
    const float* to_out_w  = (const float*)d_in[11];
    const float* ff_g      = (const float*)d_in[12];
    const float* ff_tw     = (const float*)d_in[13];
    const float* ff_tb     = (const float*)d_in[14];
    const float* ff_in_w   = (const float*)d_in[15];
    const float* ff_in_b   = (const float*)d_in[16];
    const float* ff_out_w  = (const float*)d_in[17];
    const float* ff_out_b  = (const float*)d_in[18];

    float *tact, *scsh_a, *scsh_f;
    __half *xn, *xh, *q, *kv, *ao, *hb, *wq, *wkv, *wo, *wfi, *wfo;
    cudaGetSymbolAddress((void**)&tact, g_tact);
    cudaGetSymbolAddress((void**)&scsh_a, g_scsh_a);
    cudaGetSymbolAddress((void**)&scsh_f, g_scsh_f);
    cudaGetSymbolAddress((void**)&xn, g_xn);
    cudaGetSymbolAddress((void**)&xh, g_xh);
    cudaGetSymbolAddress((void**)&q, g_q);
    cudaGetSymbolAddress((void**)&kv, g_kv);
    cudaGetSymbolAddress((void**)&ao, g_ao);
    cudaGetSymbolAddress((void**)&hb, g_hb);
    cudaGetSymbolAddress((void**)&wq, g_wq);
    cudaGetSymbolAddress((void**)&wkv, g_wkv);
    cudaGetSymbolAddress((void**)&wo, g_wo);
    cudaGetSymbolAddress((void**)&wfi, g_wfi);
    cudaGetSymbolAddress((void**)&wfo, g_wfo);

    cudaFuncSetAttribute(hgemm_k, cudaFuncAttributeMaxDynamicSharedMemorySize,
                         HG_SMEM);
    cudaFuncSetAttribute(qkv_k, cudaFuncAttributeMaxDynamicSharedMemorySize,
                         HG_SMEM);
    cudaFuncSetAttribute(flash_k, cudaFuncAttributeMaxDynamicSharedMemorySize,
                         FLASH_SMEM);

    float* x = (float*)d_out;
    const int M = BB * NN;

    prep_w_k<<<DEPTHL * 3072, 256>>>(to_q_w, wq, to_kv_w, wkv, to_out_w, wo,
                                     ff_in_w, wfi, ff_out_w, wfo);
    prep_x_k<<<8193, 256>>>(x_in, seq_mask, x, time_in, tact);
    time_all_k<<<dim3((2 * DIMC + 2 * INNERC) / 64, BB, DEPTHL), 256>>>(
        tact, attn_tw, attn_tb, ff_tw, ff_tb, scsh_a, scsh_f);

    for (int d = 0; d < DEPTHL; d++) {
        // --- attention block ---
        ln_mod_k<<<M / 8, 256>>>(x, attn_g + d * DIMC,
                                 scsh_a + (size_t)d * BB * 2 * DIMC, seq_mask,
                                 xn, xh, 1);
        qkv_k<<<dim3(12, M / 128), 256, HG_SMEM>>>(
            xn, xh, wq + (size_t)d * DIMC * HIDD, wkv + (size_t)d * DIMC * 2 * HIDD,
            q, kv);
        flash_k<<<dim3(NN / 128, BB * HEADS), 256, FLASH_SMEM>>>(
            q, kv, res_idx, seq_mask, relpos_w, relpos_b, ao);
        hgemm_k<<<dim3(DIMC / 128, M / 128), 256, HG_SMEM>>>(
            ao, wo + (size_t)d * HIDD * DIMC, x, DIMC, HIDD,
            nullptr, x, seq_mask, nullptr, 1.f, 2);

        // --- feed-forward block ---
        ln_mod_k<<<M / 8, 256>>>(x, ff_g + d * DIMC, nullptr, nullptr, xn, nullptr, 0);
        hgemm_k<<<dim3(INNERC / 128, M / 128), 256, HG_SMEM>>>(
            xn, wfi + (size_t)d * DIMC * INNERC, hb, INNERC, DIMC,
            ff_in_b + (size_t)d * INNERC, nullptr, nullptr,
            scsh_f + (size_t)d * BB * 2 * INNERC, 1.f, 1);
        hgemm_k<<<dim3(DIMC / 128, M / 128), 256, HG_SMEM>>>(
            hb, wfo + (size_t)d * INNERC * DIMC, x, DIMC, INNERC,
            ff_out_b + (size_t)d * DIMC, x, seq_mask, nullptr, 1.f, 3);
    }
}